// round 5
// baseline (speedup 1.0000x reference)
#include <cuda_runtime.h>
#include <cstdint>

#define Nn 100000
#define Ee 800000
typedef unsigned long long ull;

// ---------------- scratch (static __device__ globals; no runtime alloc) ----------------
__device__ int   g_is64;
__device__ int   g_degi[Nn];
__device__ float g_dinv[Nn];
__device__ float g_cinv[Nn];
__device__ int   g_rowptr[Nn + 1];
__device__ int   g_fill[Nn];
__device__ int   g_colidx[Ee];
__device__ float g_hA[(size_t)Nn * 256];
__device__ float g_hB[(size_t)Nn * 256];
__device__ float g_agg[(size_t)Nn * 256];

// ---------------- packed f32x2 helpers ----------------
__device__ __forceinline__ ull pack2(float x, float y) {
    ull r;
    asm("mov.b64 %0, {%1, %2};" : "=l"(r) : "f"(x), "f"(y));
    return r;
}
__device__ __forceinline__ void unpack2(ull v, float& x, float& y) {
    asm("mov.b64 {%0, %1}, %2;" : "=f"(x), "=f"(y) : "l"(v));
}
__device__ __forceinline__ ull ffma2(ull a, ull b, ull c) {
    ull d;
    asm("fma.rn.f32x2 %0, %1, %2, %3;" : "=l"(d) : "l"(a), "l"(b), "l"(c));
    return d;
}

// ---------------- dtype detection: int32 vs int64 edge_index ----------------
__global__ void k_detect(const int* __restrict__ w) {
    if (threadIdx.x == 0 && blockIdx.x == 0) {
        int is64 = 1;
        for (int i = 0; i < 256; i++)
            if (w[2 * i + 1] != 0) { is64 = 0; break; }
        g_is64 = is64;
    }
}

__device__ __forceinline__ int edge_at(const void* ei, int half, int e) {
    if (g_is64) return (int)((const long long*)ei)[(size_t)half * Ee + e];
    return ((const int*)ei)[(size_t)half * Ee + e];
}

// ---------------- small kernels ----------------
__global__ void k_zero(int* p, int n) {
    int i = blockIdx.x * blockDim.x + threadIdx.x;
    if (i < n) p[i] = 0;
}

__global__ void k_count(const void* __restrict__ ei, int* __restrict__ degi) {
    int e = blockIdx.x * blockDim.x + threadIdx.x;
    if (e < Ee) atomicAdd(&degi[edge_at(ei, 0, e)], 1);
}

__global__ void k_stats(const int* __restrict__ degi, float* __restrict__ dinv,
                        float* __restrict__ cinv) {
    int i = blockIdx.x * blockDim.x + threadIdx.x;
    if (i < Nn) {
        int d = degi[i];
        dinv[i] = (d > 0) ? rsqrtf((float)d) : 0.0f;
        cinv[i] = 1.0f / (float)max(d, 1);
    }
}

__global__ void k_scan(const int* __restrict__ cnt, int* __restrict__ rowptr,
                       int* __restrict__ fill) {
    __shared__ int wsum[32];
    __shared__ int carry;
    int tid = threadIdx.x, lane = tid & 31, wid = tid >> 5;
    if (tid == 0) carry = 0;
    __syncthreads();
    for (int base = 0; base < Nn; base += 1024) {
        int i = base + tid;
        int v = (i < Nn) ? cnt[i] : 0;
        int inc = v;
        #pragma unroll
        for (int o = 1; o < 32; o <<= 1) {
            int t = __shfl_up_sync(0xFFFFFFFFu, inc, o);
            if (lane >= o) inc += t;
        }
        if (lane == 31) wsum[wid] = inc;
        __syncthreads();
        if (wid == 0) {
            int s = wsum[lane];
            #pragma unroll
            for (int o = 1; o < 32; o <<= 1) {
                int t = __shfl_up_sync(0xFFFFFFFFu, s, o);
                if (lane >= o) s += t;
            }
            wsum[lane] = s;
        }
        __syncthreads();
        int woff  = wid ? wsum[wid - 1] : 0;
        int total = wsum[31];
        int ex = carry + woff + inc - v;
        if (i < Nn) { rowptr[i] = ex; fill[i] = ex; }
        __syncthreads();
        if (tid == 0) carry += total;
        __syncthreads();
    }
    if (threadIdx.x == 0) rowptr[Nn] = carry;
}

__global__ void k_fill(const void* __restrict__ ei, int* __restrict__ fill,
                       int* __restrict__ colidx) {
    int e = blockIdx.x * blockDim.x + threadIdx.x;
    if (e < Ee) {
        int r = edge_at(ei, 0, e);
        int c = edge_at(ei, 1, e);
        int p = atomicAdd(&fill[r], 1);
        colidx[p] = c;
    }
}

// ---------------- aggregation (CSR gather-sum) ----------------
template <int C, bool GCN>
__global__ void k_agg(const float* __restrict__ h, float* __restrict__ out,
                      const int* __restrict__ rowptr, const int* __restrict__ colidx,
                      const float* __restrict__ dinv, const float* __restrict__ cinv) {
    constexpr int TPN = C / 4;
    constexpr int NPB = 256 / TPN;
    int node = blockIdx.x * NPB + threadIdx.x / TPN;
    if (node >= Nn) return;
    int lane = threadIdx.x % TPN;
    int s = rowptr[node], e = rowptr[node + 1];
    const float4* h4 = (const float4*)h;
    float4 acc = make_float4(0.f, 0.f, 0.f, 0.f);
    for (int p = s; p < e; p++) {
        int j = colidx[p];
        float w = GCN ? dinv[j] : 1.0f;
        float4 v = __ldg(&h4[(size_t)j * TPN + lane]);
        acc.x += v.x * w; acc.y += v.y * w; acc.z += v.z * w; acc.w += v.w * w;
    }
    float sc = GCN ? dinv[node] : cinv[node];
    acc.x *= sc; acc.y *= sc; acc.z *= sc; acc.w *= sc;
    ((float4*)out)[(size_t)node * TPN + lane] = acc;
}

// ---------------- fused dual GEMM via packed f32x2 FFMA, 64x128 tile ----------------
// out = epi(A0@B0 [+ A1@B1] + bias); epi: relu or rezero-residual
#define BM 64
#define BN 128
#define BK 16
__global__ void __launch_bounds__(256, 2)
k_gemm(const float* __restrict__ A0, const float* __restrict__ B0,
       const float* __restrict__ A1, const float* __restrict__ B1,
       const float* __restrict__ bias,
       const float* __restrict__ res, const float* __restrict__ alphaPtr, int alphaIdx,
       float* __restrict__ out, int n, int K, int Cout, int doRelu) {
    __shared__ __align__(16) ull   sAp[BK][BM];   // A as duplicated (a,a) pairs: 8KB
    __shared__ __align__(16) float sB[BK][BN];    // 8KB
    int bm = blockIdx.y * BM;
    int bn = blockIdx.x * BN;
    int tx = threadIdx.x % 16;   // n-groups: cols tx*4..+3 and 64+tx*4..+3
    int ty = threadIdx.x / 16;   // m-group: rows ty*4..+3

    ull acc[4][4];
    #pragma unroll
    for (int i = 0; i < 4; i++)
        #pragma unroll
        for (int j = 0; j < 4; j++) acc[i][j] = 0ull;

    #pragma unroll 1
    for (int pass = 0; pass < 2; pass++) {
        const float* A = pass ? A1 : A0;
        const float* B = pass ? B1 : B0;
        if (!A) continue;
        #pragma unroll 1
        for (int k0 = 0; k0 < K; k0 += BK) {
            // A tile: 64 rows x 16 k; one float4 per thread, stored as (a,a) pairs
            {
                int row = threadIdx.x / 4;
                int k4  = (threadIdx.x % 4) * 4;
                int gr = bm + row;
                float4 v = make_float4(0.f, 0.f, 0.f, 0.f);
                if (gr < n) v = *(const float4*)&A[(size_t)gr * K + k0 + k4];
                sAp[k4 + 0][row] = pack2(v.x, v.x);
                sAp[k4 + 1][row] = pack2(v.y, v.y);
                sAp[k4 + 2][row] = pack2(v.z, v.z);
                sAp[k4 + 3][row] = pack2(v.w, v.w);
            }
            // B tile: 16 k x 128 n; two float4 per thread
            {
                int kk = threadIdx.x / 32;        // 0..7
                int n4 = (threadIdx.x % 32) * 4;  // 0..124
                int gc = bn + n4;
                float4 z = make_float4(0.f, 0.f, 0.f, 0.f);
                float4 v0 = (gc < Cout) ? *(const float4*)&B[(size_t)(k0 + kk) * Cout + gc] : z;
                float4 v1 = (gc < Cout) ? *(const float4*)&B[(size_t)(k0 + kk + 8) * Cout + gc] : z;
                *(float4*)&sB[kk][n4]     = v0;
                *(float4*)&sB[kk + 8][n4] = v1;
            }
            __syncthreads();
            #pragma unroll
            for (int kk = 0; kk < BK; kk++) {
                ulonglong2 bL  = *(const ulonglong2*)&sB[kk][tx * 4];
                ulonglong2 bH  = *(const ulonglong2*)&sB[kk][64 + tx * 4];
                ulonglong2 a01 = *(const ulonglong2*)&sAp[kk][ty * 4 + 0];
                ulonglong2 a23 = *(const ulonglong2*)&sAp[kk][ty * 4 + 2];
                ull a[4] = {a01.x, a01.y, a23.x, a23.y};
                #pragma unroll
                for (int mi = 0; mi < 4; mi++) {
                    acc[mi][0] = ffma2(a[mi], bL.x, acc[mi][0]);
                    acc[mi][1] = ffma2(a[mi], bL.y, acc[mi][1]);
                    acc[mi][2] = ffma2(a[mi], bH.x, acc[mi][2]);
                    acc[mi][3] = ffma2(a[mi], bH.y, acc[mi][3]);
                }
            }
            __syncthreads();
        }
    }

    float alpha = alphaPtr ? __ldg(&alphaPtr[alphaIdx]) : 0.f;
    #pragma unroll
    for (int mi = 0; mi < 4; mi++) {
        int gr = bm + ty * 4 + mi;
        if (gr >= n) continue;
        #pragma unroll
        for (int half = 0; half < 2; half++) {
            int gc0 = bn + half * 64 + tx * 4;
            float v[4];
            unpack2(acc[mi][half * 2 + 0], v[0], v[1]);
            unpack2(acc[mi][half * 2 + 1], v[2], v[3]);
            if (gc0 + 3 < Cout) {
                float4 bv = *(const float4*)&bias[gc0];
                float4 o;
                o.x = v[0] + bv.x; o.y = v[1] + bv.y; o.z = v[2] + bv.z; o.w = v[3] + bv.w;
                if (doRelu) {
                    o.x = fmaxf(o.x, 0.f); o.y = fmaxf(o.y, 0.f);
                    o.z = fmaxf(o.z, 0.f); o.w = fmaxf(o.w, 0.f);
                }
                if (res) {
                    float4 rv = *(const float4*)&res[(size_t)gr * Cout + gc0];
                    o.x = rv.x + alpha * o.x; o.y = rv.y + alpha * o.y;
                    o.z = rv.z + alpha * o.z; o.w = rv.w + alpha * o.w;
                }
                *(float4*)&out[(size_t)gr * Cout + gc0] = o;
            } else {
                #pragma unroll
                for (int u = 0; u < 4; u++) {
                    int gc = gc0 + u;
                    if (gc >= Cout) continue;
                    float val = v[u] + __ldg(&bias[gc]);
                    if (doRelu) val = fmaxf(val, 0.f);
                    if (res) val = res[(size_t)gr * Cout + gc] + alpha * val;
                    out[(size_t)gr * Cout + gc] = val;
                }
            }
        }
    }
}

// ---------------- launch ----------------
extern "C" void kernel_launch(void* const* d_in, const int* in_sizes, int n_in,
                              void* d_out, int out_size) {
    const float* x     = (const float*)d_in[0];
    const void*  ei    = d_in[1];
    const float* alpha = (const float*)d_in[2];
    const float* W0 = (const float*)d_in[3];  const float* b0 = (const float*)d_in[4];
    const float* W1 = (const float*)d_in[5];  const float* R1 = (const float*)d_in[6];  const float* b1 = (const float*)d_in[7];
    const float* W2 = (const float*)d_in[8];  const float* R2 = (const float*)d_in[9];  const float* b2 = (const float*)d_in[10];
    const float* W3 = (const float*)d_in[11]; const float* b3 = (const float*)d_in[12];
    const float* W4 = (const float*)d_in[13]; const float* R4 = (const float*)d_in[14]; const float* b4 = (const float*)d_in[15];
    float* out = (float*)d_out;

    float *hA, *hB, *agg, *dinv, *cinv;
    int *degi, *rowptr, *fill, *colidx;
    cudaGetSymbolAddress((void**)&degi,   g_degi);
    cudaGetSymbolAddress((void**)&dinv,   g_dinv);
    cudaGetSymbolAddress((void**)&cinv,   g_cinv);
    cudaGetSymbolAddress((void**)&rowptr, g_rowptr);
    cudaGetSymbolAddress((void**)&fill,   g_fill);
    cudaGetSymbolAddress((void**)&colidx, g_colidx);
    cudaGetSymbolAddress((void**)&hA,     g_hA);
    cudaGetSymbolAddress((void**)&hB,     g_hB);
    cudaGetSymbolAddress((void**)&agg,    g_agg);

    const int NB_N = (Nn + 255) / 256;
    const int NB_E = (Ee + 255) / 256;
    const int MT   = (Nn + BM - 1) / BM;   // 1563

    k_detect<<<1, 32>>>((const int*)ei);
    k_zero<<<NB_N, 256>>>(degi, Nn);
    k_count<<<NB_E, 256>>>(ei, degi);
    k_stats<<<NB_N, 256>>>(degi, dinv, cinv);
    k_scan<<<1, 1024>>>(degi, rowptr, fill);
    k_fill<<<NB_E, 256>>>(ei, fill, colidx);

    // layer 0: GCN, C=128, rezero residual (alpha[0])
    k_agg<128, true><<<Nn / 8, 256>>>(x, agg, rowptr, colidx, dinv, cinv);
    k_gemm<<<dim3(1, MT), 256>>>(agg, W0, nullptr, nullptr, b0, x, alpha, 0, hA, Nn, 128, 128, 0);

    // layer 1: SAGE 128->256 + relu
    k_agg<128, false><<<Nn / 8, 256>>>(hA, agg, rowptr, colidx, dinv, cinv);
    k_gemm<<<dim3(2, MT), 256>>>(agg, W1, hA, R1, b1, nullptr, nullptr, 0, hB, Nn, 128, 256, 1);

    // layer 2: SAGE 256->256 + relu
    k_agg<256, false><<<Nn / 4, 256>>>(hB, agg, rowptr, colidx, dinv, cinv);
    k_gemm<<<dim3(2, MT), 256>>>(agg, W2, hB, R2, b2, nullptr, nullptr, 0, hA, Nn, 256, 256, 1);

    // layer 3: GCN, C=256, rezero residual (alpha[3])
    k_agg<256, true><<<Nn / 4, 256>>>(hA, agg, rowptr, colidx, dinv, cinv);
    k_gemm<<<dim3(2, MT), 256>>>(agg, W3, nullptr, nullptr, b3, hA, alpha, 3, hB, Nn, 256, 256, 0);

    // layer 4: SAGE 256->112, no relu
    k_agg<256, false><<<Nn / 4, 256>>>(hB, agg, rowptr, colidx, dinv, cinv);
    k_gemm<<<dim3(1, MT), 256>>>(agg, W4, hB, R4, b4, nullptr, nullptr, 0, out, Nn, 256, 112, 0);
}

// round 7
// speedup vs baseline: 1.8996x; 1.8996x over previous
#include <cuda_runtime.h>
#include <cstdint>

#define Nn 100000
#define Ee 800000

// ---------------- scratch (static __device__ globals; no runtime alloc) ----------------
__device__ int   g_is64;
__device__ int   g_degi[Nn];
__device__ float g_dinv[Nn];
__device__ float g_cinv[Nn];
__device__ int   g_rowptr[Nn + 1];
__device__ int   g_fill[Nn];
__device__ int   g_colidx[Ee];
__device__ float g_hA[(size_t)Nn * 256];
__device__ float g_hB[(size_t)Nn * 256];
__device__ float g_agg[(size_t)Nn * 256];

__device__ __forceinline__ uint32_t f2tf32(float x) {
    uint32_t u;
    asm("cvt.rna.tf32.f32 %0, %1;" : "=r"(u) : "f"(x));
    return u;
}
__device__ __forceinline__ void mma8(float* d, const uint32_t* a, const uint32_t* b) {
    asm volatile(
        "mma.sync.aligned.m16n8k8.row.col.f32.tf32.tf32.f32 "
        "{%0,%1,%2,%3}, {%4,%5,%6,%7}, {%8,%9}, {%0,%1,%2,%3};"
        : "+f"(d[0]), "+f"(d[1]), "+f"(d[2]), "+f"(d[3])
        : "r"(a[0]), "r"(a[1]), "r"(a[2]), "r"(a[3]), "r"(b[0]), "r"(b[1]));
}

// ---------------- dtype detection: int32 vs int64 edge_index ----------------
__global__ void k_detect(const int* __restrict__ w) {
    if (threadIdx.x == 0 && blockIdx.x == 0) {
        int is64 = 1;
        for (int i = 0; i < 256; i++)
            if (w[2 * i + 1] != 0) { is64 = 0; break; }
        g_is64 = is64;
    }
}
__device__ __forceinline__ int edge_at(const void* ei, int half, int e) {
    if (g_is64) return (int)((const long long*)ei)[(size_t)half * Ee + e];
    return ((const int*)ei)[(size_t)half * Ee + e];
}

// ---------------- small kernels ----------------
__global__ void k_zero(int* p, int n) {
    int i = blockIdx.x * blockDim.x + threadIdx.x;
    if (i < n) p[i] = 0;
}
__global__ void k_count(const void* __restrict__ ei, int* __restrict__ degi) {
    int e = blockIdx.x * blockDim.x + threadIdx.x;
    if (e < Ee) atomicAdd(&degi[edge_at(ei, 0, e)], 1);
}
__global__ void k_stats(const int* __restrict__ degi, float* __restrict__ dinv,
                        float* __restrict__ cinv) {
    int i = blockIdx.x * blockDim.x + threadIdx.x;
    if (i < Nn) {
        int d = degi[i];
        dinv[i] = (d > 0) ? rsqrtf((float)d) : 0.0f;
        cinv[i] = 1.0f / (float)max(d, 1);
    }
}
__global__ void k_scan(const int* __restrict__ cnt, int* __restrict__ rowptr,
                       int* __restrict__ fill) {
    __shared__ int wsum[32];
    __shared__ int carry;
    int tid = threadIdx.x, lane = tid & 31, wid = tid >> 5;
    if (tid == 0) carry = 0;
    __syncthreads();
    for (int base = 0; base < Nn; base += 1024) {
        int i = base + tid;
        int v = (i < Nn) ? cnt[i] : 0;
        int inc = v;
        #pragma unroll
        for (int o = 1; o < 32; o <<= 1) {
            int t = __shfl_up_sync(0xFFFFFFFFu, inc, o);
            if (lane >= o) inc += t;
        }
        if (lane == 31) wsum[wid] = inc;
        __syncthreads();
        if (wid == 0) {
            int s = wsum[lane];
            #pragma unroll
            for (int o = 1; o < 32; o <<= 1) {
                int t = __shfl_up_sync(0xFFFFFFFFu, s, o);
                if (lane >= o) s += t;
            }
            wsum[lane] = s;
        }
        __syncthreads();
        int woff  = wid ? wsum[wid - 1] : 0;
        int total = wsum[31];
        int ex = carry + woff + inc - v;
        if (i < Nn) { rowptr[i] = ex; fill[i] = ex; }
        __syncthreads();
        if (tid == 0) carry += total;
        __syncthreads();
    }
    if (threadIdx.x == 0) rowptr[Nn] = carry;
}
__global__ void k_fill(const void* __restrict__ ei, int* __restrict__ fill,
                       int* __restrict__ colidx) {
    int e = blockIdx.x * blockDim.x + threadIdx.x;
    if (e < Ee) {
        int r = edge_at(ei, 0, e);
        int c = edge_at(ei, 1, e);
        int p = atomicAdd(&fill[r], 1);
        colidx[p] = c;
    }
}

// ---------------- aggregation (CSR gather-sum) ----------------
template <int C, bool GCN>
__global__ void k_agg(const float* __restrict__ h, float* __restrict__ out,
                      const int* __restrict__ rowptr, const int* __restrict__ colidx,
                      const float* __restrict__ dinv, const float* __restrict__ cinv) {
    constexpr int TPN = C / 4;
    constexpr int NPB = 256 / TPN;
    int node = blockIdx.x * NPB + threadIdx.x / TPN;
    if (node >= Nn) return;
    int lane = threadIdx.x % TPN;
    int s = rowptr[node], e = rowptr[node + 1];
    const float4* h4 = (const float4*)h;
    float4 acc = make_float4(0.f, 0.f, 0.f, 0.f);
    for (int p = s; p < e; p++) {
        int j = colidx[p];
        float w = GCN ? dinv[j] : 1.0f;
        float4 v = __ldg(&h4[(size_t)j * TPN + lane]);
        acc.x += v.x * w; acc.y += v.y * w; acc.z += v.z * w; acc.w += v.w * w;
    }
    float sc = GCN ? dinv[node] : cinv[node];
    acc.x *= sc; acc.y *= sc; acc.z *= sc; acc.w *= sc;
    ((float4*)out)[(size_t)node * TPN + lane] = acc;
}

// ---------------- tensor-core tf32 dual GEMM: out = epi(A0@B0 [+ A1@B1] + bias) ----------------
// block 128x128, 8 warps 4(M)x2(N), warp tile 32x64 via m16n8k8 atoms
#define TM 128
#define TN 128
#define TK 32
__global__ void __launch_bounds__(256)
k_gemm_tc(const float* __restrict__ A0, const float* __restrict__ B0,
          const float* __restrict__ A1, const float* __restrict__ B1,
          const float* __restrict__ bias,
          const float* __restrict__ res, const float* __restrict__ alphaPtr, int alphaIdx,
          float* __restrict__ out, int n, int K, int Cout, int doRelu) {
    __shared__ uint32_t sA[TM][36];   // [m][k] pad->bank (4m+k)%32, conflict-free frags
    __shared__ uint32_t sB[TK][132];  // [k][n] pad->bank (4k+n)%32, conflict-free frags
    int tid = threadIdx.x, lane = tid & 31, wid = tid >> 5;
    int gid = lane >> 2, tig = lane & 3;
    int warp_m = wid >> 1, warp_n = wid & 1;
    int bm = blockIdx.y * TM, bn = blockIdx.x * TN;

    float acc[2][8][4];
    #pragma unroll
    for (int i = 0; i < 2; i++)
        #pragma unroll
        for (int j = 0; j < 8; j++)
            #pragma unroll
            for (int u = 0; u < 4; u++) acc[i][j][u] = 0.f;

    int nPass = A1 ? 2 : 1;
    #pragma unroll 1
    for (int pass = 0; pass < nPass; pass++) {
        const float* A = pass ? A1 : A0;
        const float* B = pass ? B1 : B0;
        #pragma unroll 1
        for (int k0 = 0; k0 < K; k0 += TK) {
            __syncthreads();
            // A tile: 128 rows x 32 k; each thread 4 float4 along k (2 threads/row)
            {
                int row = tid >> 1, kq = (tid & 1) * 16;
                int gr = bm + row;
                #pragma unroll
                for (int i = 0; i < 4; i++) {
                    float4 v = make_float4(0.f, 0.f, 0.f, 0.f);
                    if (gr < n) v = *(const float4*)&A[(size_t)gr * K + k0 + kq + i * 4];
                    uint32_t* dst = &sA[row][kq + i * 4];
                    dst[0] = f2tf32(v.x); dst[1] = f2tf32(v.y);
                    dst[2] = f2tf32(v.z); dst[3] = f2tf32(v.w);
                }
            }
            // B tile: 32 k x 128 n; each thread 4 rows of one float4
            {
                int nn = (tid & 31) * 4;
                int kb = (tid >> 5) * 4;
                int gc = bn + nn;
                #pragma unroll
                for (int i = 0; i < 4; i++) {
                    int k = kb + i;
                    float4 v = make_float4(0.f, 0.f, 0.f, 0.f);
                    if (gc + 3 < Cout) {
                        v = *(const float4*)&B[(size_t)(k0 + k) * Cout + gc];
                    } else if (gc < Cout) {
                        v.x = B[(size_t)(k0 + k) * Cout + gc];
                        if (gc + 1 < Cout) v.y = B[(size_t)(k0 + k) * Cout + gc + 1];
                        if (gc + 2 < Cout) v.z = B[(size_t)(k0 + k) * Cout + gc + 2];
                    }
                    uint32_t* dst = &sB[k][nn];
                    dst[0] = f2tf32(v.x); dst[1] = f2tf32(v.y);
                    dst[2] = f2tf32(v.z); dst[3] = f2tf32(v.w);
                }
            }
            __syncthreads();
            #pragma unroll
            for (int ks = 0; ks < 4; ks++) {
                int k8 = ks * 8;
                uint32_t af[2][4];
                #pragma unroll
                for (int ma = 0; ma < 2; ma++) {
                    int m0 = warp_m * 32 + ma * 16;
                    af[ma][0] = sA[m0 + gid][k8 + tig];
                    af[ma][1] = sA[m0 + gid + 8][k8 + tig];
                    af[ma][2] = sA[m0 + gid][k8 + tig + 4];
                    af[ma][3] = sA[m0 + gid + 8][k8 + tig + 4];
                }
                #pragma unroll
                for (int na = 0; na < 8; na++) {
                    int n0 = warp_n * 64 + na * 8;
                    uint32_t bf[2];
                    bf[0] = sB[k8 + tig][n0 + gid];
                    bf[1] = sB[k8 + tig + 4][n0 + gid];
                    mma8(acc[0][na], af[0], bf);
                    mma8(acc[1][na], af[1], bf);
                }
            }
        }
    }

    float alpha = alphaPtr ? __ldg(&alphaPtr[alphaIdx]) : 0.f;
    #pragma unroll
    for (int ma = 0; ma < 2; ma++) {
        #pragma unroll
        for (int na = 0; na < 8; na++) {
            int gc = bn + warp_n * 64 + na * 8 + tig * 2;
            #pragma unroll
            for (int half = 0; half < 2; half++) {
                int gr = bm + warp_m * 32 + ma * 16 + gid + half * 8;
                if (gr >= n) continue;
                float v0 = acc[ma][na][half * 2 + 0];
                float v1 = acc[ma][na][half * 2 + 1];
                if (gc + 1 < Cout) {
                    v0 += __ldg(&bias[gc]);
                    v1 += __ldg(&bias[gc + 1]);
                    if (doRelu) { v0 = fmaxf(v0, 0.f); v1 = fmaxf(v1, 0.f); }
                    if (res) {
                        const float2 rv = *(const float2*)&res[(size_t)gr * Cout + gc];
                        v0 = rv.x + alpha * v0;
                        v1 = rv.y + alpha * v1;
                    }
                    float2 o; o.x = v0; o.y = v1;
                    *(float2*)&out[(size_t)gr * Cout + gc] = o;
                } else if (gc < Cout) {
                    v0 += __ldg(&bias[gc]);
                    if (doRelu) v0 = fmaxf(v0, 0.f);
                    if (res) v0 = res[(size_t)gr * Cout + gc] + alpha * v0;
                    out[(size_t)gr * Cout + gc] = v0;
                }
            }
        }
    }
}

// ---------------- launch ----------------
extern "C" void kernel_launch(void* const* d_in, const int* in_sizes, int n_in,
                              void* d_out, int out_size) {
    const float* x     = (const float*)d_in[0];
    const void*  ei    = d_in[1];
    const float* alpha = (const float*)d_in[2];
    const float* W0 = (const float*)d_in[3];  const float* b0 = (const float*)d_in[4];
    const float* W1 = (const float*)d_in[5];  const float* R1 = (const float*)d_in[6];  const float* b1 = (const float*)d_in[7];
    const float* W2 = (const float*)d_in[8];  const float* R2 = (const float*)d_in[9];  const float* b2 = (const float*)d_in[10];
    const float* W3 = (const float*)d_in[11]; const float* b3 = (const float*)d_in[12];
    const float* W4 = (const float*)d_in[13]; const float* R4 = (const float*)d_in[14]; const float* b4 = (const float*)d_in[15];
    float* out = (float*)d_out;

    float *hA, *hB, *agg, *dinv, *cinv;
    int *degi, *rowptr, *fill, *colidx;
    cudaGetSymbolAddress((void**)&degi,   g_degi);
    cudaGetSymbolAddress((void**)&dinv,   g_dinv);
    cudaGetSymbolAddress((void**)&cinv,   g_cinv);
    cudaGetSymbolAddress((void**)&rowptr, g_rowptr);
    cudaGetSymbolAddress((void**)&fill,   g_fill);
    cudaGetSymbolAddress((void**)&colidx, g_colidx);
    cudaGetSymbolAddress((void**)&hA,     g_hA);
    cudaGetSymbolAddress((void**)&hB,     g_hB);
    cudaGetSymbolAddress((void**)&agg,    g_agg);

    const int NB_N = (Nn + 255) / 256;
    const int NB_E = (Ee + 255) / 256;
    const int MT   = (Nn + TM - 1) / TM;   // 782

    k_detect<<<1, 32>>>((const int*)ei);
    k_zero<<<NB_N, 256>>>(degi, Nn);
    k_count<<<NB_E, 256>>>(ei, degi);
    k_stats<<<NB_N, 256>>>(degi, dinv, cinv);
    k_scan<<<1, 1024>>>(degi, rowptr, fill);
    k_fill<<<NB_E, 256>>>(ei, fill, colidx);

    // layer 0: GCN, 128->128, rezero residual alpha[0]
    k_agg<128, true><<<Nn / 8, 256>>>(x, agg, rowptr, colidx, dinv, cinv);
    k_gemm_tc<<<dim3(1, MT), 256>>>(agg, W0, nullptr, nullptr, b0, x, alpha, 0, hA,
                                    Nn, 128, 128, 0);

    // layer 1: SAGE 128->256 + relu
    k_agg<128, false><<<Nn / 8, 256>>>(hA, agg, rowptr, colidx, dinv, cinv);
    k_gemm_tc<<<dim3(2, MT), 256>>>(agg, W1, hA, R1, b1, nullptr, nullptr, 0, hB,
                                    Nn, 128, 256, 1);

    // layer 2: SAGE 256->256 + relu
    k_agg<256, false><<<Nn / 4, 256>>>(hB, agg, rowptr, colidx, dinv, cinv);
    k_gemm_tc<<<dim3(2, MT), 256>>>(agg, W2, hB, R2, b2, nullptr, nullptr, 0, hA,
                                    Nn, 256, 256, 1);

    // layer 3: GCN, 256->256, rezero residual alpha[3]
    k_agg<256, true><<<Nn / 4, 256>>>(hA, agg, rowptr, colidx, dinv, cinv);
    k_gemm_tc<<<dim3(2, MT), 256>>>(agg, W3, nullptr, nullptr, b3, hA, alpha, 3, hB,
                                    Nn, 256, 256, 0);

    // layer 4: SAGE 256->112, no relu
    k_agg<256, false><<<Nn / 4, 256>>>(hB, agg, rowptr, colidx, dinv, cinv);
    k_gemm_tc<<<dim3(1, MT), 256>>>(agg, W4, hB, R4, b4, nullptr, nullptr, 0, out,
                                    Nn, 256, 112, 0);
}

// round 9
// speedup vs baseline: 2.0176x; 1.0621x over previous
#include <cuda_runtime.h>
#include <cstdint>

#define Nn 100000
#define Ee 800000

// ---------------- scratch (static __device__ globals; no runtime alloc) ----------------
__device__ int   g_is64;
__device__ int   g_degi[Nn];
__device__ float g_dinv[Nn];
__device__ float g_cinv[Nn];
__device__ int   g_rowptr[Nn + 1];
__device__ int   g_fill[Nn];
__device__ int   g_colidx[Ee];
__device__ float g_hA [(size_t)Nn * 256];
__device__ float g_hB [(size_t)Nn * 256];
__device__ float g_hAT[(size_t)Nn * 256];
__device__ float g_hBT[(size_t)Nn * 256];
__device__ float g_agg[(size_t)Nn * 256];
#define WTF_TOTAL 335872
__device__ float g_wtf[WTF_TOTAL];

__device__ __forceinline__ uint32_t f2tf32(float x) {
    uint32_t u;
    asm("cvt.rna.tf32.f32 %0, %1;" : "=r"(u) : "f"(x));
    return u;
}
__device__ __forceinline__ float tff(float x) { return __uint_as_float(f2tf32(x)); }
__device__ __forceinline__ void mma8(float* d, const uint32_t* a, const uint32_t* b) {
    asm volatile(
        "mma.sync.aligned.m16n8k8.row.col.f32.tf32.tf32.f32 "
        "{%0,%1,%2,%3}, {%4,%5,%6,%7}, {%8,%9}, {%0,%1,%2,%3};"
        : "+f"(d[0]), "+f"(d[1]), "+f"(d[2]), "+f"(d[3])
        : "r"(a[0]), "r"(a[1]), "r"(a[2]), "r"(a[3]), "r"(b[0]), "r"(b[1]));
}

// ---------------- weight pre-conversion to tf32 ----------------
__global__ void k_cvtW(const float* __restrict__ W0, const float* __restrict__ W1,
                       const float* __restrict__ R1, const float* __restrict__ W2,
                       const float* __restrict__ R2, const float* __restrict__ W3,
                       const float* __restrict__ W4, const float* __restrict__ R4) {
    int i = blockIdx.x * blockDim.x + threadIdx.x;
    if (i >= WTF_TOTAL) return;
    const float* s; int off;
    if      (i < 16384)  { s = W0; off = 0; }
    else if (i < 49152)  { s = W1; off = 16384; }
    else if (i < 81920)  { s = R1; off = 49152; }
    else if (i < 147456) { s = W2; off = 81920; }
    else if (i < 212992) { s = R2; off = 147456; }
    else if (i < 278528) { s = W3; off = 212992; }
    else if (i < 307200) { s = W4; off = 278528; }
    else                 { s = R4; off = 307200; }
    g_wtf[i] = tff(s[i - off]);
}

// ---------------- dtype detection: int32 vs int64 edge_index ----------------
__global__ void k_detect(const int* __restrict__ w) {
    if (threadIdx.x == 0 && blockIdx.x == 0) {
        int is64 = 1;
        for (int i = 0; i < 256; i++)
            if (w[2 * i + 1] != 0) { is64 = 0; break; }
        g_is64 = is64;
    }
}
__device__ __forceinline__ int edge_at(const void* ei, int half, int e) {
    if (g_is64) return (int)((const long long*)ei)[(size_t)half * Ee + e];
    return ((const int*)ei)[(size_t)half * Ee + e];
}

// ---------------- small kernels ----------------
__global__ void k_zero(int* p, int n) {
    int i = blockIdx.x * blockDim.x + threadIdx.x;
    if (i < n) p[i] = 0;
}
__global__ void k_count(const void* __restrict__ ei, int* __restrict__ degi) {
    int e = blockIdx.x * blockDim.x + threadIdx.x;
    if (e < Ee) atomicAdd(&degi[edge_at(ei, 0, e)], 1);
}
__global__ void k_stats(const int* __restrict__ degi, float* __restrict__ dinv,
                        float* __restrict__ cinv) {
    int i = blockIdx.x * blockDim.x + threadIdx.x;
    if (i < Nn) {
        int d = degi[i];
        dinv[i] = (d > 0) ? rsqrtf((float)d) : 0.0f;
        cinv[i] = 1.0f / (float)max(d, 1);
    }
}
__global__ void k_scan(const int* __restrict__ cnt, int* __restrict__ rowptr,
                       int* __restrict__ fill) {
    __shared__ int wsum[32];
    __shared__ int carry;
    int tid = threadIdx.x, lane = tid & 31, wid = tid >> 5;
    if (tid == 0) carry = 0;
    __syncthreads();
    for (int base = 0; base < Nn; base += 1024) {
        int i = base + tid;
        int v = (i < Nn) ? cnt[i] : 0;
        int inc = v;
        #pragma unroll
        for (int o = 1; o < 32; o <<= 1) {
            int t = __shfl_up_sync(0xFFFFFFFFu, inc, o);
            if (lane >= o) inc += t;
        }
        if (lane == 31) wsum[wid] = inc;
        __syncthreads();
        if (wid == 0) {
            int s = wsum[lane];
            #pragma unroll
            for (int o = 1; o < 32; o <<= 1) {
                int t = __shfl_up_sync(0xFFFFFFFFu, s, o);
                if (lane >= o) s += t;
            }
            wsum[lane] = s;
        }
        __syncthreads();
        int woff  = wid ? wsum[wid - 1] : 0;
        int total = wsum[31];
        int ex = carry + woff + inc - v;
        if (i < Nn) { rowptr[i] = ex; fill[i] = ex; }
        __syncthreads();
        if (tid == 0) carry += total;
        __syncthreads();
    }
    if (threadIdx.x == 0) rowptr[Nn] = carry;
}
__global__ void k_fill(const void* __restrict__ ei, int* __restrict__ fill,
                       int* __restrict__ colidx) {
    int e = blockIdx.x * blockDim.x + threadIdx.x;
    if (e < Ee) {
        int r = edge_at(ei, 0, e);
        int c = edge_at(ei, 1, e);
        int p = atomicAdd(&fill[r], 1);
        colidx[p] = c;
    }
}

// ---------------- aggregation (CSR gather-sum) -> tf32 output ----------------
template <int C, bool GCN>
__global__ void k_agg(const float* __restrict__ h, float* __restrict__ out,
                      const int* __restrict__ rowptr, const int* __restrict__ colidx,
                      const float* __restrict__ dinv, const float* __restrict__ cinv) {
    constexpr int TPN = C / 4;
    constexpr int NPB = 256 / TPN;
    int node = blockIdx.x * NPB + threadIdx.x / TPN;
    if (node >= Nn) return;
    int lane = threadIdx.x % TPN;
    int s = rowptr[node], e = rowptr[node + 1];
    const float4* h4 = (const float4*)h;
    float4 acc = make_float4(0.f, 0.f, 0.f, 0.f);
    for (int p = s; p < e; p++) {
        int j = colidx[p];
        float w = GCN ? dinv[j] : 1.0f;
        float4 v = __ldg(&h4[(size_t)j * TPN + lane]);
        acc.x += v.x * w; acc.y += v.y * w; acc.z += v.z * w; acc.w += v.w * w;
    }
    float sc = GCN ? dinv[node] : cinv[node];
    float4 o;
    o.x = tff(acc.x * sc); o.y = tff(acc.y * sc);
    o.z = tff(acc.z * sc); o.w = tff(acc.w * sc);
    ((float4*)out)[(size_t)node * TPN + lane] = o;
}

// ---------------- tensor-core tf32 dual GEMM: out = epi(A0@B0 [+ A1@B1] + bias) ----------------
// A/B inputs are ALREADY tf32-valued fp32; loader is pure LDG.128/STS.128.
// block 128x128, 8 warps 4(M)x2(N), warp tile 32x64 via m16n8k8 atoms
#define TM 128
#define TN 128
#define TK 32
__global__ void __launch_bounds__(256)
k_gemm_tc(const float* __restrict__ A0, const float* __restrict__ B0,
          const float* __restrict__ A1, const float* __restrict__ B1,
          const float* __restrict__ bias,
          const float* __restrict__ res, const float* __restrict__ alphaPtr, int alphaIdx,
          float* __restrict__ out, float* __restrict__ outT,
          int n, int K, int Cout, int doRelu) {
    __shared__ uint32_t sA[TM][36];   // [m][k]
    __shared__ uint32_t sB[TK][132];  // [k][n]
    int tid = threadIdx.x, lane = tid & 31, wid = tid >> 5;
    int gid = lane >> 2, tig = lane & 3;
    int warp_m = wid >> 1, warp_n = wid & 1;
    int bm = blockIdx.y * TM, bn = blockIdx.x * TN;

    float acc[2][8][4];
    #pragma unroll
    for (int i = 0; i < 2; i++)
        #pragma unroll
        for (int j = 0; j < 8; j++)
            #pragma unroll
            for (int u = 0; u < 4; u++) acc[i][j][u] = 0.f;

    int nPass = A1 ? 2 : 1;
    #pragma unroll 1
    for (int pass = 0; pass < nPass; pass++) {
        const float* A = pass ? A1 : A0;
        const float* B = pass ? B1 : B0;
        #pragma unroll 1
        for (int k0 = 0; k0 < K; k0 += TK) {
            __syncthreads();
            // A tile: 128 rows x 32 k; LDG.128 -> STS.128
            {
                int row = tid >> 1, kq = (tid & 1) * 16;
                int gr = bm + row;
                #pragma unroll
                for (int i = 0; i < 4; i++) {
                    uint4 v = make_uint4(0u, 0u, 0u, 0u);
                    if (gr < n) v = *(const uint4*)&A[(size_t)gr * K + k0 + kq + i * 4];
                    *(uint4*)&sA[row][kq + i * 4] = v;
                }
            }
            // B tile: 32 k x 128 n; LDG.128 -> STS.128 (Cout always %4==0)
            {
                int nn = (tid & 31) * 4;
                int kb = (tid >> 5) * 4;
                int gc = bn + nn;
                #pragma unroll
                for (int i = 0; i < 4; i++) {
                    uint4 v = make_uint4(0u, 0u, 0u, 0u);
                    if (gc + 3 < Cout)
                        v = *(const uint4*)&B[(size_t)(k0 + kb + i) * Cout + gc];
                    *(uint4*)&sB[kb + i][nn] = v;
                }
            }
            __syncthreads();
            #pragma unroll
            for (int ks = 0; ks < 4; ks++) {
                int k8 = ks * 8;
                uint32_t af[2][4];
                #pragma unroll
                for (int ma = 0; ma < 2; ma++) {
                    int m0 = warp_m * 32 + ma * 16;
                    af[ma][0] = sA[m0 + gid][k8 + tig];
                    af[ma][1] = sA[m0 + gid + 8][k8 + tig];
                    af[ma][2] = sA[m0 + gid][k8 + tig + 4];
                    af[ma][3] = sA[m0 + gid + 8][k8 + tig + 4];
                }
                #pragma unroll
                for (int na = 0; na < 8; na++) {
                    int n0 = warp_n * 64 + na * 8;
                    uint32_t bf[2];
                    bf[0] = sB[k8 + tig][n0 + gid];
                    bf[1] = sB[k8 + tig + 4][n0 + gid];
                    mma8(acc[0][na], af[0], bf);
                    mma8(acc[1][na], af[1], bf);
                }
            }
        }
    }

    float alpha = alphaPtr ? __ldg(&alphaPtr[alphaIdx]) : 0.f;
    #pragma unroll
    for (int ma = 0; ma < 2; ma++) {
        #pragma unroll
        for (int na = 0; na < 8; na++) {
            int gc = bn + warp_n * 64 + na * 8 + tig * 2;
            #pragma unroll
            for (int half = 0; half < 2; half++) {
                int gr = bm + warp_m * 32 + ma * 16 + gid + half * 8;
                if (gr >= n) continue;
                float v0 = acc[ma][na][half * 2 + 0];
                float v1 = acc[ma][na][half * 2 + 1];
                if (gc + 1 < Cout) {
                    v0 += __ldg(&bias[gc]);
                    v1 += __ldg(&bias[gc + 1]);
                    if (doRelu) { v0 = fmaxf(v0, 0.f); v1 = fmaxf(v1, 0.f); }
                    if (res) {
                        const float2 rv = *(const float2*)&res[(size_t)gr * Cout + gc];
                        v0 = rv.x + alpha * v0;
                        v1 = rv.y + alpha * v1;
                    }
                    float2 o; o.x = v0; o.y = v1;
                    *(float2*)&out[(size_t)gr * Cout + gc] = o;
                    if (outT) {
                        float2 t; t.x = tff(v0); t.y = tff(v1);
                        *(float2*)&outT[(size_t)gr * Cout + gc] = t;
                    }
                } else if (gc < Cout) {
                    v0 += __ldg(&bias[gc]);
                    if (doRelu) v0 = fmaxf(v0, 0.f);
                    if (res) v0 = res[(size_t)gr * Cout + gc] + alpha * v0;
                    out[(size_t)gr * Cout + gc] = v0;
                    if (outT) outT[(size_t)gr * Cout + gc] = tff(v0);
                }
            }
        }
    }
}

// ---------------- launch ----------------
extern "C" void kernel_launch(void* const* d_in, const int* in_sizes, int n_in,
                              void* d_out, int out_size) {
    const float* x     = (const float*)d_in[0];
    const void*  ei    = d_in[1];
    const float* alpha = (const float*)d_in[2];
    const float* W0 = (const float*)d_in[3];  const float* b0 = (const float*)d_in[4];
    const float* W1 = (const float*)d_in[5];  const float* R1 = (const float*)d_in[6];  const float* b1 = (const float*)d_in[7];
    const float* W2 = (const float*)d_in[8];  const float* R2 = (const float*)d_in[9];  const float* b2 = (const float*)d_in[10];
    const float* W3 = (const float*)d_in[11]; const float* b3 = (const float*)d_in[12];
    const float* W4 = (const float*)d_in[13]; const float* R4 = (const float*)d_in[14]; const float* b4 = (const float*)d_in[15];
    float* out = (float*)d_out;

    float *hA, *hB, *hAT, *hBT, *agg, *dinv, *cinv, *wtf;
    int *degi, *rowptr, *fill, *colidx;
    cudaGetSymbolAddress((void**)&degi,   g_degi);
    cudaGetSymbolAddress((void**)&dinv,   g_dinv);
    cudaGetSymbolAddress((void**)&cinv,   g_cinv);
    cudaGetSymbolAddress((void**)&rowptr, g_rowptr);
    cudaGetSymbolAddress((void**)&fill,   g_fill);
    cudaGetSymbolAddress((void**)&colidx, g_colidx);
    cudaGetSymbolAddress((void**)&hA,     g_hA);
    cudaGetSymbolAddress((void**)&hB,     g_hB);
    cudaGetSymbolAddress((void**)&hAT,    g_hAT);
    cudaGetSymbolAddress((void**)&hBT,    g_hBT);
    cudaGetSymbolAddress((void**)&agg,    g_agg);
    cudaGetSymbolAddress((void**)&wtf,    g_wtf);

    const int NB_N = (Nn + 255) / 256;
    const int NB_E = (Ee + 255) / 256;
    const int MT   = (Nn + TM - 1) / TM;   // 782

    k_detect<<<1, 32>>>((const int*)ei);
    k_cvtW<<<(WTF_TOTAL + 255) / 256, 256>>>(W0, W1, R1, W2, R2, W3, W4, R4);
    k_zero<<<NB_N, 256>>>(degi, Nn);
    k_count<<<NB_E, 256>>>(ei, degi);
    k_stats<<<NB_N, 256>>>(degi, dinv, cinv);
    k_scan<<<1, 1024>>>(degi, rowptr, fill);
    k_fill<<<NB_E, 256>>>(ei, fill, colidx);

    // layer 0: GCN, 128->128, rezero residual alpha[0]; hA + tf32 copy (A1 of L1)
    k_agg<128, true><<<Nn / 8, 256>>>(x, agg, rowptr, colidx, dinv, cinv);
    k_gemm_tc<<<dim3(1, MT), 256>>>(agg, wtf + 0, nullptr, nullptr, b0, x, alpha, 0,
                                    hA, hAT, Nn, 128, 128, 0);

    // layer 1: SAGE 128->256 + relu; hB + tf32 copy (A1 of L2)
    k_agg<128, false><<<Nn / 8, 256>>>(hA, agg, rowptr, colidx, dinv, cinv);
    k_gemm_tc<<<dim3(2, MT), 256>>>(agg, wtf + 16384, hAT, wtf + 49152, b1,
                                    nullptr, nullptr, 0, hB, hBT, Nn, 128, 256, 1);

    // layer 2: SAGE 256->256 + relu; hA (L3 needs fp32 only)
    k_agg<256, false><<<Nn / 4, 256>>>(hB, agg, rowptr, colidx, dinv, cinv);
    k_gemm_tc<<<dim3(2, MT), 256>>>(agg, wtf + 81920, hBT, wtf + 147456, b2,
                                    nullptr, nullptr, 0, hA, nullptr, Nn, 256, 256, 1);

    // layer 3: GCN, 256->256, rezero residual alpha[3]; hB + tf32 copy (A1 of L4)
    k_agg<256, true><<<Nn / 4, 256>>>(hA, agg, rowptr, colidx, dinv, cinv);
    k_gemm_tc<<<dim3(2, MT), 256>>>(agg, wtf + 212992, nullptr, nullptr, b3,
                                    hA, alpha, 3, hB, hBT, Nn, 256, 256, 0);

    // layer 4: SAGE 256->112, no relu
    k_agg<256, false><<<Nn / 4, 256>>>(hB, agg, rowptr, colidx, dinv, cinv);
    k_gemm_tc<<<dim3(1, MT), 256>>>(agg, wtf + 278528, hBT, wtf + 307200, b4,
                                    nullptr, nullptr, 0, out, nullptr, Nn, 256, 112, 0);
}

// round 10
// speedup vs baseline: 2.0582x; 1.0201x over previous
#include <cuda_runtime.h>
#include <cstdint>

#define Nn 100000
#define Ee 800000

// ---------------- scratch (static __device__ globals; no runtime alloc) ----------------
__device__ int   g_is64;
__device__ int   g_degi[Nn];
__device__ float g_dinv[Nn];
__device__ float g_cinv[Nn];
__device__ int   g_rowptr[Nn + 1];
__device__ int   g_fill[Nn];
__device__ int   g_colidx[Ee];
__device__ float g_hA [(size_t)Nn * 256];
__device__ float g_hB [(size_t)Nn * 256];
__device__ float g_hAT[(size_t)Nn * 256];
__device__ float g_hBT[(size_t)Nn * 256];
__device__ float g_agg[(size_t)Nn * 256];
#define WTF_TOTAL 335872
__device__ float g_wtf[WTF_TOTAL];

__device__ __forceinline__ uint32_t f2tf32(float x) {
    uint32_t u;
    asm("cvt.rna.tf32.f32 %0, %1;" : "=r"(u) : "f"(x));
    return u;
}
__device__ __forceinline__ float tff(float x) { return __uint_as_float(f2tf32(x)); }
__device__ __forceinline__ void mma8(float* d, const uint32_t* a, const uint32_t* b) {
    asm volatile(
        "mma.sync.aligned.m16n8k8.row.col.f32.tf32.tf32.f32 "
        "{%0,%1,%2,%3}, {%4,%5,%6,%7}, {%8,%9}, {%0,%1,%2,%3};"
        : "+f"(d[0]), "+f"(d[1]), "+f"(d[2]), "+f"(d[3])
        : "r"(a[0]), "r"(a[1]), "r"(a[2]), "r"(a[3]), "r"(b[0]), "r"(b[1]));
}
__device__ __forceinline__ uint32_t smem_u32(const void* p) {
    uint32_t a;
    asm("{ .reg .u64 t; cvta.to.shared.u64 t, %1; cvt.u32.u64 %0, t; }" : "=r"(a) : "l"(p));
    return a;
}
__device__ __forceinline__ void cpa16(uint32_t s, const void* g) {
    asm volatile("cp.async.ca.shared.global [%0], [%1], 16;" :: "r"(s), "l"(g));
}

// ---------------- weight pre-conversion to tf32 ----------------
__global__ void k_cvtW(const float* __restrict__ W0, const float* __restrict__ W1,
                       const float* __restrict__ R1, const float* __restrict__ W2,
                       const float* __restrict__ R2, const float* __restrict__ W3,
                       const float* __restrict__ W4, const float* __restrict__ R4) {
    int i = blockIdx.x * blockDim.x + threadIdx.x;
    if (i >= WTF_TOTAL) return;
    const float* s; int off;
    if      (i < 16384)  { s = W0; off = 0; }
    else if (i < 49152)  { s = W1; off = 16384; }
    else if (i < 81920)  { s = R1; off = 49152; }
    else if (i < 147456) { s = W2; off = 81920; }
    else if (i < 212992) { s = R2; off = 147456; }
    else if (i < 278528) { s = W3; off = 212992; }
    else if (i < 307200) { s = W4; off = 278528; }
    else                 { s = R4; off = 307200; }
    g_wtf[i] = tff(s[i - off]);
}

// ---------------- dtype detection: int32 vs int64 edge_index ----------------
__global__ void k_detect(const int* __restrict__ w) {
    if (threadIdx.x == 0 && blockIdx.x == 0) {
        int is64 = 1;
        for (int i = 0; i < 256; i++)
            if (w[2 * i + 1] != 0) { is64 = 0; break; }
        g_is64 = is64;
    }
}
__device__ __forceinline__ int edge_at(const void* ei, int half, int e) {
    if (g_is64) return (int)((const long long*)ei)[(size_t)half * Ee + e];
    return ((const int*)ei)[(size_t)half * Ee + e];
}

// ---------------- small kernels ----------------
__global__ void k_zero(int* p, int n) {
    int i = blockIdx.x * blockDim.x + threadIdx.x;
    if (i < n) p[i] = 0;
}
__global__ void k_count(const void* __restrict__ ei, int* __restrict__ degi) {
    int e = blockIdx.x * blockDim.x + threadIdx.x;
    if (e < Ee) atomicAdd(&degi[edge_at(ei, 0, e)], 1);
}
__global__ void k_stats(const int* __restrict__ degi, float* __restrict__ dinv,
                        float* __restrict__ cinv) {
    int i = blockIdx.x * blockDim.x + threadIdx.x;
    if (i < Nn) {
        int d = degi[i];
        dinv[i] = (d > 0) ? rsqrtf((float)d) : 0.0f;
        cinv[i] = 1.0f / (float)max(d, 1);
    }
}
__global__ void k_scan(const int* __restrict__ cnt, int* __restrict__ rowptr,
                       int* __restrict__ fill) {
    __shared__ int wsum[32];
    __shared__ int carry;
    int tid = threadIdx.x, lane = tid & 31, wid = tid >> 5;
    if (tid == 0) carry = 0;
    __syncthreads();
    for (int base = 0; base < Nn; base += 1024) {
        int i = base + tid;
        int v = (i < Nn) ? cnt[i] : 0;
        int inc = v;
        #pragma unroll
        for (int o = 1; o < 32; o <<= 1) {
            int t = __shfl_up_sync(0xFFFFFFFFu, inc, o);
            if (lane >= o) inc += t;
        }
        if (lane == 31) wsum[wid] = inc;
        __syncthreads();
        if (wid == 0) {
            int s = wsum[lane];
            #pragma unroll
            for (int o = 1; o < 32; o <<= 1) {
                int t = __shfl_up_sync(0xFFFFFFFFu, s, o);
                if (lane >= o) s += t;
            }
            wsum[lane] = s;
        }
        __syncthreads();
        int woff  = wid ? wsum[wid - 1] : 0;
        int total = wsum[31];
        int ex = carry + woff + inc - v;
        if (i < Nn) { rowptr[i] = ex; fill[i] = ex; }
        __syncthreads();
        if (tid == 0) carry += total;
        __syncthreads();
    }
    if (threadIdx.x == 0) rowptr[Nn] = carry;
}
__global__ void k_fill(const void* __restrict__ ei, int* __restrict__ fill,
                       int* __restrict__ colidx) {
    int e = blockIdx.x * blockDim.x + threadIdx.x;
    if (e < Ee) {
        int r = edge_at(ei, 0, e);
        int c = edge_at(ei, 1, e);
        int p = atomicAdd(&fill[r], 1);
        colidx[p] = c;
    }
}

// ---------------- aggregation (CSR gather-sum) -> tf32 output ----------------
template <int C, bool GCN>
__global__ void k_agg(const float* __restrict__ h, float* __restrict__ out,
                      const int* __restrict__ rowptr, const int* __restrict__ colidx,
                      const float* __restrict__ dinv, const float* __restrict__ cinv) {
    constexpr int TPN = C / 4;
    constexpr int NPB = 256 / TPN;
    int node = blockIdx.x * NPB + threadIdx.x / TPN;
    if (node >= Nn) return;
    int lane = threadIdx.x % TPN;
    int s = rowptr[node], e = rowptr[node + 1];
    const float4* h4 = (const float4*)h;
    float4 acc = make_float4(0.f, 0.f, 0.f, 0.f);
    for (int p = s; p < e; p++) {
        int j = colidx[p];
        float w = GCN ? dinv[j] : 1.0f;
        float4 v = __ldg(&h4[(size_t)j * TPN + lane]);
        acc.x += v.x * w; acc.y += v.y * w; acc.z += v.z * w; acc.w += v.w * w;
    }
    float sc = GCN ? dinv[node] : cinv[node];
    float4 o;
    o.x = tff(acc.x * sc); o.y = tff(acc.y * sc);
    o.z = tff(acc.z * sc); o.w = tff(acc.w * sc);
    ((float4*)out)[(size_t)node * TPN + lane] = o;
}

// ---------------- cp.async double-buffered tf32 dual GEMM ----------------
// block 128x128, 8 warps 4(M)x2(N), warp tile 32x64 via m16n8k8 atoms
#define TM 128
#define TN 128
#define TK 32
#define STG_W 8832            // words per stage: 128*36 + 32*132
#define SB_OFF 4608           // sB word offset within stage
#define SMEM_GT (2 * STG_W * 4)

__global__ void __launch_bounds__(256)
k_gemm_tc(const float* __restrict__ A0, const float* __restrict__ B0,
          const float* __restrict__ A1, const float* __restrict__ B1,
          const float* __restrict__ bias,
          const float* __restrict__ res, const float* __restrict__ alphaPtr, int alphaIdx,
          float* __restrict__ out, float* __restrict__ outT,
          int n, int K, int Cout, int doRelu) {
    extern __shared__ uint32_t smem[];
    int tid = threadIdx.x, lane = tid & 31, wid = tid >> 5;
    int gid = lane >> 2, tig = lane & 3;
    int warp_m = wid >> 1, warp_n = wid & 1;
    int bm = blockIdx.y * TM, bn = blockIdx.x * TN;

    // per-thread load coords
    int arow = tid >> 1, akq = (tid & 1) * 16;
    int agr = min(bm + arow, n - 1);                    // clamp: OOB rows never stored
    int bnn = (tid & 31) * 4, bkb = (tid >> 5) * 4;
    int bgc = min(bn + bnn, Cout - 4);                  // clamp: OOB cols never stored
    uint32_t sbase = smem_u32(smem);

    int nc0 = K / TK;
    int nc = A1 ? 2 * nc0 : nc0;

    // prefetch lambda (macro-style)
    #define PREFETCH(ci, buf) do { \
        int _p = (ci) >= nc0; \
        const float* _A = _p ? A1 : A0; \
        const float* _B = _p ? B1 : B0; \
        int _k0 = ((ci) - _p * nc0) * TK; \
        uint32_t _sa = sbase + ((buf) * STG_W + arow * 36 + akq) * 4; \
        const float* _ga = &_A[(size_t)agr * K + _k0 + akq]; \
        cpa16(_sa,      _ga); \
        cpa16(_sa + 16, _ga + 4); \
        cpa16(_sa + 32, _ga + 8); \
        cpa16(_sa + 48, _ga + 12); \
        uint32_t _sb = sbase + ((buf) * STG_W + SB_OFF + bkb * 132 + bnn) * 4; \
        const float* _gb = &_B[(size_t)(_k0 + bkb) * Cout + bgc]; \
        cpa16(_sb,            _gb); \
        cpa16(_sb + 132 * 4,  _gb + Cout); \
        cpa16(_sb + 264 * 4,  _gb + 2 * Cout); \
        cpa16(_sb + 396 * 4,  _gb + 3 * Cout); \
        asm volatile("cp.async.commit_group;"); \
    } while (0)

    float acc[2][8][4];
    #pragma unroll
    for (int i = 0; i < 2; i++)
        #pragma unroll
        for (int j = 0; j < 8; j++)
            #pragma unroll
            for (int u = 0; u < 4; u++) acc[i][j][u] = 0.f;

    PREFETCH(0, 0);
    #pragma unroll 1
    for (int ci = 0; ci < nc; ci++) {
        int buf = ci & 1;
        if (ci + 1 < nc) {
            PREFETCH(ci + 1, buf ^ 1);
            asm volatile("cp.async.wait_group 1;");
        } else {
            asm volatile("cp.async.wait_group 0;");
        }
        __syncthreads();
        const uint32_t* sAb = smem + buf * STG_W;
        const uint32_t* sBb = smem + buf * STG_W + SB_OFF;
        #pragma unroll
        for (int ks = 0; ks < 4; ks++) {
            int k8 = ks * 8;
            uint32_t af[2][4];
            #pragma unroll
            for (int ma = 0; ma < 2; ma++) {
                int m0 = warp_m * 32 + ma * 16;
                af[ma][0] = sAb[(m0 + gid) * 36 + k8 + tig];
                af[ma][1] = sAb[(m0 + gid + 8) * 36 + k8 + tig];
                af[ma][2] = sAb[(m0 + gid) * 36 + k8 + tig + 4];
                af[ma][3] = sAb[(m0 + gid + 8) * 36 + k8 + tig + 4];
            }
            #pragma unroll
            for (int na = 0; na < 8; na++) {
                int n0 = warp_n * 64 + na * 8;
                uint32_t bf[2];
                bf[0] = sBb[(k8 + tig) * 132 + n0 + gid];
                bf[1] = sBb[(k8 + tig + 4) * 132 + n0 + gid];
                mma8(acc[0][na], af[0], bf);
                mma8(acc[1][na], af[1], bf);
            }
        }
        __syncthreads();
    }
    #undef PREFETCH

    float alpha = alphaPtr ? __ldg(&alphaPtr[alphaIdx]) : 0.f;
    #pragma unroll
    for (int ma = 0; ma < 2; ma++) {
        #pragma unroll
        for (int na = 0; na < 8; na++) {
            int gc = bn + warp_n * 64 + na * 8 + tig * 2;
            #pragma unroll
            for (int half = 0; half < 2; half++) {
                int gr = bm + warp_m * 32 + ma * 16 + gid + half * 8;
                if (gr >= n) continue;
                float v0 = acc[ma][na][half * 2 + 0];
                float v1 = acc[ma][na][half * 2 + 1];
                if (gc + 1 < Cout) {
                    v0 += __ldg(&bias[gc]);
                    v1 += __ldg(&bias[gc + 1]);
                    if (doRelu) { v0 = fmaxf(v0, 0.f); v1 = fmaxf(v1, 0.f); }
                    if (res) {
                        const float2 rv = *(const float2*)&res[(size_t)gr * Cout + gc];
                        v0 = rv.x + alpha * v0;
                        v1 = rv.y + alpha * v1;
                    }
                    float2 o; o.x = v0; o.y = v1;
                    *(float2*)&out[(size_t)gr * Cout + gc] = o;
                    if (outT) {
                        float2 t; t.x = tff(v0); t.y = tff(v1);
                        *(float2*)&outT[(size_t)gr * Cout + gc] = t;
                    }
                } else if (gc < Cout) {
                    v0 += __ldg(&bias[gc]);
                    if (doRelu) v0 = fmaxf(v0, 0.f);
                    if (res) v0 = res[(size_t)gr * Cout + gc] + alpha * v0;
                    out[(size_t)gr * Cout + gc] = v0;
                    if (outT) outT[(size_t)gr * Cout + gc] = tff(v0);
                }
            }
        }
    }
}

// ---------------- launch ----------------
extern "C" void kernel_launch(void* const* d_in, const int* in_sizes, int n_in,
                              void* d_out, int out_size) {
    const float* x     = (const float*)d_in[0];
    const void*  ei    = d_in[1];
    const float* alpha = (const float*)d_in[2];
    const float* W0 = (const float*)d_in[3];  const float* b0 = (const float*)d_in[4];
    const float* W1 = (const float*)d_in[5];  const float* R1 = (const float*)d_in[6];  const float* b1 = (const float*)d_in[7];
    const float* W2 = (const float*)d_in[8];  const float* R2 = (const float*)d_in[9];  const float* b2 = (const float*)d_in[10];
    const float* W3 = (const float*)d_in[11]; const float* b3 = (const float*)d_in[12];
    const float* W4 = (const float*)d_in[13]; const float* R4 = (const float*)d_in[14]; const float* b4 = (const float*)d_in[15];
    float* out = (float*)d_out;

    float *hA, *hB, *hAT, *hBT, *agg, *dinv, *cinv, *wtf;
    int *degi, *rowptr, *fill, *colidx;
    cudaGetSymbolAddress((void**)&degi,   g_degi);
    cudaGetSymbolAddress((void**)&dinv,   g_dinv);
    cudaGetSymbolAddress((void**)&cinv,   g_cinv);
    cudaGetSymbolAddress((void**)&rowptr, g_rowptr);
    cudaGetSymbolAddress((void**)&fill,   g_fill);
    cudaGetSymbolAddress((void**)&colidx, g_colidx);
    cudaGetSymbolAddress((void**)&hA,     g_hA);
    cudaGetSymbolAddress((void**)&hB,     g_hB);
    cudaGetSymbolAddress((void**)&hAT,    g_hAT);
    cudaGetSymbolAddress((void**)&hBT,    g_hBT);
    cudaGetSymbolAddress((void**)&agg,    g_agg);
    cudaGetSymbolAddress((void**)&wtf,    g_wtf);

    cudaFuncSetAttribute(k_gemm_tc, cudaFuncAttributeMaxDynamicSharedMemorySize, SMEM_GT);

    const int NB_N = (Nn + 255) / 256;
    const int NB_E = (Ee + 255) / 256;
    const int MT   = (Nn + TM - 1) / TM;   // 782

    k_detect<<<1, 32>>>((const int*)ei);
    k_cvtW<<<(WTF_TOTAL + 255) / 256, 256>>>(W0, W1, R1, W2, R2, W3, W4, R4);
    k_zero<<<NB_N, 256>>>(degi, Nn);
    k_count<<<NB_E, 256>>>(ei, degi);
    k_stats<<<NB_N, 256>>>(degi, dinv, cinv);
    k_scan<<<1, 1024>>>(degi, rowptr, fill);
    k_fill<<<NB_E, 256>>>(ei, fill, colidx);

    // layer 0: GCN, 128->128, rezero residual alpha[0]; hA + tf32 copy
    k_agg<128, true><<<Nn / 8, 256>>>(x, agg, rowptr, colidx, dinv, cinv);
    k_gemm_tc<<<dim3(1, MT), 256, SMEM_GT>>>(agg, wtf + 0, nullptr, nullptr, b0, x, alpha, 0,
                                             hA, hAT, Nn, 128, 128, 0);

    // layer 1: SAGE 128->256 + relu; hB + tf32 copy
    k_agg<128, false><<<Nn / 8, 256>>>(hA, agg, rowptr, colidx, dinv, cinv);
    k_gemm_tc<<<dim3(2, MT), 256, SMEM_GT>>>(agg, wtf + 16384, hAT, wtf + 49152, b1,
                                             nullptr, nullptr, 0, hB, hBT, Nn, 128, 256, 1);

    // layer 2: SAGE 256->256 + relu; hA (fp32 only)
    k_agg<256, false><<<Nn / 4, 256>>>(hB, agg, rowptr, colidx, dinv, cinv);
    k_gemm_tc<<<dim3(2, MT), 256, SMEM_GT>>>(agg, wtf + 81920, hBT, wtf + 147456, b2,
                                             nullptr, nullptr, 0, hA, nullptr, Nn, 256, 256, 1);

    // layer 3: GCN, 256->256, rezero residual alpha[3]; hB + tf32 copy
    k_agg<256, true><<<Nn / 4, 256>>>(hA, agg, rowptr, colidx, dinv, cinv);
    k_gemm_tc<<<dim3(2, MT), 256, SMEM_GT>>>(agg, wtf + 212992, nullptr, nullptr, b3,
                                             hA, alpha, 3, hB, hBT, Nn, 256, 256, 0);

    // layer 4: SAGE 256->112, no relu
    k_agg<256, false><<<Nn / 4, 256>>>(hB, agg, rowptr, colidx, dinv, cinv);
    k_gemm_tc<<<dim3(1, MT), 256, SMEM_GT>>>(agg, wtf + 278528, hBT, wtf + 307200, b4,
                                             nullptr, nullptr, 0, out, nullptr, Nn, 256, 112, 0);
}

// round 11
// speedup vs baseline: 2.6832x; 1.3037x over previous
#include <cuda_runtime.h>
#include <cuda_fp16.h>
#include <cstdint>

#define Nn 100000
#define Ee 800000

// ---------------- scratch (static __device__ globals; no runtime alloc) ----------------
__device__ int    g_is64;
__device__ int    g_degi[Nn];
__device__ float  g_dinv[Nn];
__device__ float  g_cinv[Nn];
__device__ int    g_rowptr[Nn + 1];
__device__ int    g_fill[Nn];
__device__ int    g_colidx[Ee];
__device__ float  g_hA [(size_t)Nn * 256];
__device__ float  g_hB [(size_t)Nn * 256];
__device__ __half g_hAT[(size_t)Nn * 256];
__device__ __half g_hBT[(size_t)Nn * 256];
__device__ __half g_agg[(size_t)Nn * 256];
#define WTF_TOTAL 335872
__device__ __half g_w16[WTF_TOTAL];

__device__ __forceinline__ void mma16(float* d, const uint32_t* a, const uint32_t* b) {
    asm volatile(
        "mma.sync.aligned.m16n8k16.row.col.f32.f16.f16.f32 "
        "{%0,%1,%2,%3}, {%4,%5,%6,%7}, {%8,%9}, {%0,%1,%2,%3};"
        : "+f"(d[0]), "+f"(d[1]), "+f"(d[2]), "+f"(d[3])
        : "r"(a[0]), "r"(a[1]), "r"(a[2]), "r"(a[3]), "r"(b[0]), "r"(b[1]));
}
__device__ __forceinline__ uint32_t smem_u32(const void* p) {
    uint32_t a;
    asm("{ .reg .u64 t; cvta.to.shared.u64 t, %1; cvt.u32.u64 %0, t; }" : "=r"(a) : "l"(p));
    return a;
}
__device__ __forceinline__ void cpa16(uint32_t s, const void* g) {
    asm volatile("cp.async.ca.shared.global [%0], [%1], 16;" :: "r"(s), "l"(g));
}

// ---------------- weight pre-conversion: fp32 [k][n] -> fp16 transposed [n][k] ----------------
__global__ void k_cvtW(const float* __restrict__ W0, const float* __restrict__ W1,
                       const float* __restrict__ R1, const float* __restrict__ W2,
                       const float* __restrict__ R2, const float* __restrict__ W3,
                       const float* __restrict__ W4, const float* __restrict__ R4) {
    int i = blockIdx.x * blockDim.x + threadIdx.x;
    if (i >= WTF_TOTAL) return;
    const float* s; int off, K, C;
    if      (i < 16384)  { s = W0; off = 0;      K = 128; C = 128; }
    else if (i < 49152)  { s = W1; off = 16384;  K = 128; C = 256; }
    else if (i < 81920)  { s = R1; off = 49152;  K = 128; C = 256; }
    else if (i < 147456) { s = W2; off = 81920;  K = 256; C = 256; }
    else if (i < 212992) { s = R2; off = 147456; K = 256; C = 256; }
    else if (i < 278528) { s = W3; off = 212992; K = 256; C = 256; }
    else if (i < 307200) { s = W4; off = 278528; K = 256; C = 112; }
    else                 { s = R4; off = 307200; K = 256; C = 112; }
    int local = i - off;
    int nn = local / K, kk = local % K;
    g_w16[i] = __float2half_rn(s[(size_t)kk * C + nn]);
}

// ---------------- dtype detection: int32 vs int64 edge_index ----------------
__global__ void k_detect(const int* __restrict__ w) {
    if (threadIdx.x == 0 && blockIdx.x == 0) {
        int is64 = 1;
        for (int i = 0; i < 256; i++)
            if (w[2 * i + 1] != 0) { is64 = 0; break; }
        g_is64 = is64;
    }
}
__device__ __forceinline__ int edge_at(const void* ei, int half, int e) {
    if (g_is64) return (int)((const long long*)ei)[(size_t)half * Ee + e];
    return ((const int*)ei)[(size_t)half * Ee + e];
}

// ---------------- small kernels ----------------
__global__ void k_zero(int* p, int n) {
    int i = blockIdx.x * blockDim.x + threadIdx.x;
    if (i < n) p[i] = 0;
}
__global__ void k_count(const void* __restrict__ ei, int* __restrict__ degi) {
    int e = blockIdx.x * blockDim.x + threadIdx.x;
    if (e < Ee) atomicAdd(&degi[edge_at(ei, 0, e)], 1);
}
__global__ void k_stats(const int* __restrict__ degi, float* __restrict__ dinv,
                        float* __restrict__ cinv) {
    int i = blockIdx.x * blockDim.x + threadIdx.x;
    if (i < Nn) {
        int d = degi[i];
        dinv[i] = (d > 0) ? rsqrtf((float)d) : 0.0f;
        cinv[i] = 1.0f / (float)max(d, 1);
    }
}
__global__ void k_scan(const int* __restrict__ cnt, int* __restrict__ rowptr,
                       int* __restrict__ fill) {
    __shared__ int wsum[32];
    __shared__ int carry;
    int tid = threadIdx.x, lane = tid & 31, wid = tid >> 5;
    if (tid == 0) carry = 0;
    __syncthreads();
    for (int base = 0; base < Nn; base += 1024) {
        int i = base + tid;
        int v = (i < Nn) ? cnt[i] : 0;
        int inc = v;
        #pragma unroll
        for (int o = 1; o < 32; o <<= 1) {
            int t = __shfl_up_sync(0xFFFFFFFFu, inc, o);
            if (lane >= o) inc += t;
        }
        if (lane == 31) wsum[wid] = inc;
        __syncthreads();
        if (wid == 0) {
            int s = wsum[lane];
            #pragma unroll
            for (int o = 1; o < 32; o <<= 1) {
                int t = __shfl_up_sync(0xFFFFFFFFu, s, o);
                if (lane >= o) s += t;
            }
            wsum[lane] = s;
        }
        __syncthreads();
        int woff  = wid ? wsum[wid - 1] : 0;
        int total = wsum[31];
        int ex = carry + woff + inc - v;
        if (i < Nn) { rowptr[i] = ex; fill[i] = ex; }
        __syncthreads();
        if (tid == 0) carry += total;
        __syncthreads();
    }
    if (threadIdx.x == 0) rowptr[Nn] = carry;
}
__global__ void k_fill(const void* __restrict__ ei, int* __restrict__ fill,
                       int* __restrict__ colidx) {
    int e = blockIdx.x * blockDim.x + threadIdx.x;
    if (e < Ee) {
        int r = edge_at(ei, 0, e);
        int c = edge_at(ei, 1, e);
        int p = atomicAdd(&fill[r], 1);
        colidx[p] = c;
    }
}

// ---------------- aggregation (CSR gather-sum) -> fp16 output ----------------
template <int C, bool GCN>
__global__ void k_agg(const float* __restrict__ h, __half* __restrict__ out,
                      const int* __restrict__ rowptr, const int* __restrict__ colidx,
                      const float* __restrict__ dinv, const float* __restrict__ cinv) {
    constexpr int TPN = C / 4;
    constexpr int NPB = 256 / TPN;
    int node = blockIdx.x * NPB + threadIdx.x / TPN;
    if (node >= Nn) return;
    int lane = threadIdx.x % TPN;
    int s = rowptr[node], e = rowptr[node + 1];
    const float4* h4 = (const float4*)h;
    float4 acc = make_float4(0.f, 0.f, 0.f, 0.f);
    for (int p = s; p < e; p++) {
        int j = colidx[p];
        float w = GCN ? dinv[j] : 1.0f;
        float4 v = __ldg(&h4[(size_t)j * TPN + lane]);
        acc.x += v.x * w; acc.y += v.y * w; acc.z += v.z * w; acc.w += v.w * w;
    }
    float sc = GCN ? dinv[node] : cinv[node];
    __half2 o0 = __floats2half2_rn(acc.x * sc, acc.y * sc);
    __half2 o1 = __floats2half2_rn(acc.z * sc, acc.w * sc);
    uint2 u;
    u.x = *(uint32_t*)&o0; u.y = *(uint32_t*)&o1;
    ((uint2*)out)[(size_t)node * TPN + lane] = u;
}

// ---------------- fp16 HMMA dual GEMM, cp.async double-buffered ----------------
// A: [n,K] fp16 row-major (activations). B: [Cout,K] fp16 (transposed weights).
// block 128x128, 8 warps 4(M)x2(N), warp tile 32x64 via m16n8k16 atoms.
#define TM 128
#define TN 128
#define TK 32
#define ROWW 20               // words per smem row (40 halves, conflict-free)
#define SB_OFF 2560           // sB word offset within stage (128*20)
#define STG_W 5120            // words per stage
#define SMEM_GT (2 * STG_W * 4)

__global__ void __launch_bounds__(256)
k_gemm_tc(const __half* __restrict__ A0, const __half* __restrict__ B0,
          const __half* __restrict__ A1, const __half* __restrict__ B1,
          const float* __restrict__ bias,
          const float* __restrict__ res, const float* __restrict__ alphaPtr, int alphaIdx,
          float* __restrict__ out, __half* __restrict__ outT,
          int n, int K, int Cout, int doRelu) {
    extern __shared__ uint32_t smem[];
    int tid = threadIdx.x, lane = tid & 31, wid = tid >> 5;
    int gid = lane >> 2, tig = lane & 3;
    int warp_m = wid >> 1, warp_n = wid & 1;
    int bm = blockIdx.y * TM, bn = blockIdx.x * TN;

    int lrow = tid >> 1, lq = tid & 1;           // loader: 2 threads per row
    int agr = min(bm + lrow, n - 1);             // clamp: OOB rows never stored
    int bgn = min(bn + lrow, Cout - 1);          // clamp: OOB cols never stored
    uint32_t sbase = smem_u32(smem);

    int nc0 = K / TK;
    int nc = A1 ? 2 * nc0 : nc0;

    #define PREFETCH(ci, buf) do { \
        int _p = (ci) >= nc0; \
        const __half* _A = _p ? A1 : A0; \
        const __half* _B = _p ? B1 : B0; \
        int _k0 = ((ci) - _p * nc0) * TK; \
        uint32_t _sa = sbase + ((buf) * STG_W + lrow * ROWW + lq * 8) * 4; \
        const __half* _ga = &_A[(size_t)agr * K + _k0 + lq * 16]; \
        cpa16(_sa,      _ga); \
        cpa16(_sa + 16, _ga + 8); \
        uint32_t _sb = sbase + ((buf) * STG_W + SB_OFF + lrow * ROWW + lq * 8) * 4; \
        const __half* _gb = &_B[(size_t)bgn * K + _k0 + lq * 16]; \
        cpa16(_sb,      _gb); \
        cpa16(_sb + 16, _gb + 8); \
        asm volatile("cp.async.commit_group;"); \
    } while (0)

    float acc[2][8][4];
    #pragma unroll
    for (int i = 0; i < 2; i++)
        #pragma unroll
        for (int j = 0; j < 8; j++)
            #pragma unroll
            for (int u = 0; u < 4; u++) acc[i][j][u] = 0.f;

    PREFETCH(0, 0);
    #pragma unroll 1
    for (int ci = 0; ci < nc; ci++) {
        int buf = ci & 1;
        if (ci + 1 < nc) {
            PREFETCH(ci + 1, buf ^ 1);
            asm volatile("cp.async.wait_group 1;");
        } else {
            asm volatile("cp.async.wait_group 0;");
        }
        __syncthreads();
        const uint32_t* sAb = smem + buf * STG_W;
        const uint32_t* sBb = smem + buf * STG_W + SB_OFF;
        #pragma unroll
        for (int ks = 0; ks < 2; ks++) {           // two k16 steps per 32-chunk
            int kw = ks * 8;                       // word offset along k
            uint32_t af[2][4];
            #pragma unroll
            for (int ma = 0; ma < 2; ma++) {
                int m0 = warp_m * 32 + ma * 16;
                af[ma][0] = sAb[(m0 + gid) * ROWW + kw + tig];
                af[ma][1] = sAb[(m0 + gid + 8) * ROWW + kw + tig];
                af[ma][2] = sAb[(m0 + gid) * ROWW + kw + tig + 4];
                af[ma][3] = sAb[(m0 + gid + 8) * ROWW + kw + tig + 4];
            }
            #pragma unroll
            for (int na = 0; na < 8; na++) {
                int n0 = warp_n * 64 + na * 8;
                uint32_t bf[2];
                bf[0] = sBb[(n0 + gid) * ROWW + kw + tig];
                bf[1] = sBb[(n0 + gid) * ROWW + kw + tig + 4];
                mma16(acc[0][na], af[0], bf);
                mma16(acc[1][na], af[1], bf);
            }
        }
        __syncthreads();
    }
    #undef PREFETCH

    float alpha = alphaPtr ? __ldg(&alphaPtr[alphaIdx]) : 0.f;
    #pragma unroll
    for (int ma = 0; ma < 2; ma++) {
        #pragma unroll
        for (int na = 0; na < 8; na++) {
            int gc = bn + warp_n * 64 + na * 8 + tig * 2;
            #pragma unroll
            for (int half = 0; half < 2; half++) {
                int gr = bm + warp_m * 32 + ma * 16 + gid + half * 8;
                if (gr >= n) continue;
                float v0 = acc[ma][na][half * 2 + 0];
                float v1 = acc[ma][na][half * 2 + 1];
                if (gc + 1 < Cout) {
                    v0 += __ldg(&bias[gc]);
                    v1 += __ldg(&bias[gc + 1]);
                    if (doRelu) { v0 = fmaxf(v0, 0.f); v1 = fmaxf(v1, 0.f); }
                    if (res) {
                        const float2 rv = *(const float2*)&res[(size_t)gr * Cout + gc];
                        v0 = rv.x + alpha * v0;
                        v1 = rv.y + alpha * v1;
                    }
                    float2 o; o.x = v0; o.y = v1;
                    *(float2*)&out[(size_t)gr * Cout + gc] = o;
                    if (outT) {
                        __half2 t = __floats2half2_rn(v0, v1);
                        *(__half2*)&outT[(size_t)gr * Cout + gc] = t;
                    }
                } else if (gc < Cout) {
                    v0 += __ldg(&bias[gc]);
                    if (doRelu) v0 = fmaxf(v0, 0.f);
                    if (res) v0 = res[(size_t)gr * Cout + gc] + alpha * v0;
                    out[(size_t)gr * Cout + gc] = v0;
                    if (outT) outT[(size_t)gr * Cout + gc] = __float2half_rn(v0);
                }
            }
        }
    }
}

// ---------------- launch ----------------
extern "C" void kernel_launch(void* const* d_in, const int* in_sizes, int n_in,
                              void* d_out, int out_size) {
    const float* x     = (const float*)d_in[0];
    const void*  ei    = d_in[1];
    const float* alpha = (const float*)d_in[2];
    const float* W0 = (const float*)d_in[3];  const float* b0 = (const float*)d_in[4];
    const float* W1 = (const float*)d_in[5];  const float* R1 = (const float*)d_in[6];  const float* b1 = (const float*)d_in[7];
    const float* W2 = (const float*)d_in[8];  const float* R2 = (const float*)d_in[9];  const float* b2 = (const float*)d_in[10];
    const float* W3 = (const float*)d_in[11]; const float* b3 = (const float*)d_in[12];
    const float* W4 = (const float*)d_in[13]; const float* R4 = (const float*)d_in[14]; const float* b4 = (const float*)d_in[15];
    float* out = (float*)d_out;

    float *hA, *hB, *dinv, *cinv;
    __half *hAT, *hBT, *agg, *w16;
    int *degi, *rowptr, *fill, *colidx;
    cudaGetSymbolAddress((void**)&degi,   g_degi);
    cudaGetSymbolAddress((void**)&dinv,   g_dinv);
    cudaGetSymbolAddress((void**)&cinv,   g_cinv);
    cudaGetSymbolAddress((void**)&rowptr, g_rowptr);
    cudaGetSymbolAddress((void**)&fill,   g_fill);
    cudaGetSymbolAddress((void**)&colidx, g_colidx);
    cudaGetSymbolAddress((void**)&hA,     g_hA);
    cudaGetSymbolAddress((void**)&hB,     g_hB);
    cudaGetSymbolAddress((void**)&hAT,    g_hAT);
    cudaGetSymbolAddress((void**)&hBT,    g_hBT);
    cudaGetSymbolAddress((void**)&agg,    g_agg);
    cudaGetSymbolAddress((void**)&w16,    g_w16);

    cudaFuncSetAttribute(k_gemm_tc, cudaFuncAttributeMaxDynamicSharedMemorySize, SMEM_GT);

    const int NB_N = (Nn + 255) / 256;
    const int NB_E = (Ee + 255) / 256;
    const int MT   = (Nn + TM - 1) / TM;   // 782

    k_detect<<<1, 32>>>((const int*)ei);
    k_cvtW<<<(WTF_TOTAL + 255) / 256, 256>>>(W0, W1, R1, W2, R2, W3, W4, R4);
    k_zero<<<NB_N, 256>>>(degi, Nn);
    k_count<<<NB_E, 256>>>(ei, degi);
    k_stats<<<NB_N, 256>>>(degi, dinv, cinv);
    k_scan<<<1, 1024>>>(degi, rowptr, fill);
    k_fill<<<NB_E, 256>>>(ei, fill, colidx);

    // layer 0: GCN, 128->128, rezero residual alpha[0]; hA + fp16 copy
    k_agg<128, true><<<Nn / 8, 256>>>(x, agg, rowptr, colidx, dinv, cinv);
    k_gemm_tc<<<dim3(1, MT), 256, SMEM_GT>>>(agg, w16 + 0, nullptr, nullptr, b0, x, alpha, 0,
                                             hA, hAT, Nn, 128, 128, 0);

    // layer 1: SAGE 128->256 + relu; hB + fp16 copy
    k_agg<128, false><<<Nn / 8, 256>>>(hA, agg, rowptr, colidx, dinv, cinv);
    k_gemm_tc<<<dim3(2, MT), 256, SMEM_GT>>>(agg, w16 + 16384, hAT, w16 + 49152, b1,
                                             nullptr, nullptr, 0, hB, hBT, Nn, 128, 256, 1);

    // layer 2: SAGE 256->256 + relu; hA (fp32 only)
    k_agg<256, false><<<Nn / 4, 256>>>(hB, agg, rowptr, colidx, dinv, cinv);
    k_gemm_tc<<<dim3(2, MT), 256, SMEM_GT>>>(agg, w16 + 81920, hBT, w16 + 147456, b2,
                                             nullptr, nullptr, 0, hA, nullptr, Nn, 256, 256, 1);

    // layer 3: GCN, 256->256, rezero residual alpha[3]; hB + fp16 copy
    k_agg<256, true><<<Nn / 4, 256>>>(hA, agg, rowptr, colidx, dinv, cinv);
    k_gemm_tc<<<dim3(2, MT), 256, SMEM_GT>>>(agg, w16 + 212992, nullptr, nullptr, b3,
                                             hA, alpha, 3, hB, hBT, Nn, 256, 256, 0);

    // layer 4: SAGE 256->112, no relu
    k_agg<256, false><<<Nn / 4, 256>>>(hB, agg, rowptr, colidx, dinv, cinv);
    k_gemm_tc<<<dim3(1, MT), 256, SMEM_GT>>>(agg, w16 + 278528, hBT, w16 + 307200, b4,
                                             nullptr, nullptr, 0, out, nullptr, Nn, 256, 112, 0);
}

// round 13
// speedup vs baseline: 3.2278x; 1.2029x over previous
#include <cuda_runtime.h>
#include <cuda_fp16.h>
#include <cstdint>

#define Nn 100000
#define Ee 800000

// ---------------- scratch (static __device__ globals; no runtime alloc) ----------------
__device__ int    g_is64;
__device__ int    g_degi[Nn];
__device__ float  g_dinv[Nn];
__device__ float  g_cinv[Nn];
__device__ int    g_rowptr[Nn + 1];
__device__ int    g_fill[Nn];
__device__ int    g_colidx[Ee];
__device__ float  g_hA [(size_t)Nn * 256];
__device__ float  g_hB [(size_t)Nn * 256];
__device__ __half g_hAT[(size_t)Nn * 256];
__device__ __half g_hBT[(size_t)Nn * 256];
__device__ __half g_agg[(size_t)Nn * 256];
__device__ __half g_x16[(size_t)Nn * 128];
#define WTF_TOTAL 335872
__device__ __half g_w16[WTF_TOTAL];

__device__ __forceinline__ void mma16(float* d, const uint32_t* a, const uint32_t* b) {
    asm volatile(
        "mma.sync.aligned.m16n8k16.row.col.f32.f16.f16.f32 "
        "{%0,%1,%2,%3}, {%4,%5,%6,%7}, {%8,%9}, {%0,%1,%2,%3};"
        : "+f"(d[0]), "+f"(d[1]), "+f"(d[2]), "+f"(d[3])
        : "r"(a[0]), "r"(a[1]), "r"(a[2]), "r"(a[3]), "r"(b[0]), "r"(b[1]));
}
__device__ __forceinline__ uint32_t smem_u32(const void* p) {
    uint32_t a;
    asm("{ .reg .u64 t; cvta.to.shared.u64 t, %1; cvt.u32.u64 %0, t; }" : "=r"(a) : "l"(p));
    return a;
}
__device__ __forceinline__ void cpa16(uint32_t s, const void* g) {
    asm volatile("cp.async.ca.shared.global [%0], [%1], 16;" :: "r"(s), "l"(g));
}

// ---------------- weight pre-conversion: fp32 [k][n] -> fp16 transposed [n][k] ----------------
__global__ void k_cvtW(const float* __restrict__ W0, const float* __restrict__ W1,
                       const float* __restrict__ R1, const float* __restrict__ W2,
                       const float* __restrict__ R2, const float* __restrict__ W3,
                       const float* __restrict__ W4, const float* __restrict__ R4) {
    int i = blockIdx.x * blockDim.x + threadIdx.x;
    if (i >= WTF_TOTAL) return;
    const float* s; int off, K, C;
    if      (i < 16384)  { s = W0; off = 0;      K = 128; C = 128; }
    else if (i < 49152)  { s = W1; off = 16384;  K = 128; C = 256; }
    else if (i < 81920)  { s = R1; off = 49152;  K = 128; C = 256; }
    else if (i < 147456) { s = W2; off = 81920;  K = 256; C = 256; }
    else if (i < 212992) { s = R2; off = 147456; K = 256; C = 256; }
    else if (i < 278528) { s = W3; off = 212992; K = 256; C = 256; }
    else if (i < 307200) { s = W4; off = 278528; K = 256; C = 112; }
    else                 { s = R4; off = 307200; K = 256; C = 112; }
    int local = i - off;
    int nn = local / K, kk = local % K;
    g_w16[i] = __float2half_rn(s[(size_t)kk * C + nn]);
}

// ---------------- x -> fp16 (vectorized) ----------------
__global__ void k_cvtX(const float* __restrict__ x, __half* __restrict__ x16) {
    int i = blockIdx.x * blockDim.x + threadIdx.x;   // one uint4 out = 8 halves
    if (i >= Nn * 128 / 8) return;
    const float4* s = (const float4*)x;
    float4 a = __ldg(&s[2 * i]);
    float4 b = __ldg(&s[2 * i + 1]);
    __half2 h0 = __floats2half2_rn(a.x, a.y);
    __half2 h1 = __floats2half2_rn(a.z, a.w);
    __half2 h2 = __floats2half2_rn(b.x, b.y);
    __half2 h3 = __floats2half2_rn(b.z, b.w);
    uint4 u;
    u.x = *(uint32_t*)&h0; u.y = *(uint32_t*)&h1;
    u.z = *(uint32_t*)&h2; u.w = *(uint32_t*)&h3;
    ((uint4*)x16)[i] = u;
}

// ---------------- dtype detection: int32 vs int64 edge_index ----------------
__global__ void k_detect(const int* __restrict__ w) {
    if (threadIdx.x == 0 && blockIdx.x == 0) {
        int is64 = 1;
        for (int i = 0; i < 256; i++)
            if (w[2 * i + 1] != 0) { is64 = 0; break; }
        g_is64 = is64;
    }
}
__device__ __forceinline__ int edge_at(const void* ei, int half, int e) {
    if (g_is64) return (int)((const long long*)ei)[(size_t)half * Ee + e];
    return ((const int*)ei)[(size_t)half * Ee + e];
}

// ---------------- small kernels ----------------
__global__ void k_zero(int* p, int n) {
    int i = blockIdx.x * blockDim.x + threadIdx.x;
    if (i < n) p[i] = 0;
}
__global__ void k_count(const void* __restrict__ ei, int* __restrict__ degi) {
    int e = blockIdx.x * blockDim.x + threadIdx.x;
    if (e < Ee) atomicAdd(&degi[edge_at(ei, 0, e)], 1);
}
__global__ void k_stats(const int* __restrict__ degi, float* __restrict__ dinv,
                        float* __restrict__ cinv) {
    int i = blockIdx.x * blockDim.x + threadIdx.x;
    if (i < Nn) {
        int d = degi[i];
        dinv[i] = (d > 0) ? rsqrtf((float)d) : 0.0f;
        cinv[i] = 1.0f / (float)max(d, 1);
    }
}
__global__ void k_scan(const int* __restrict__ cnt, int* __restrict__ rowptr,
                       int* __restrict__ fill) {
    __shared__ int wsum[32];
    __shared__ int carry;
    int tid = threadIdx.x, lane = tid & 31, wid = tid >> 5;
    if (tid == 0) carry = 0;
    __syncthreads();
    for (int base = 0; base < Nn; base += 1024) {
        int i = base + tid;
        int v = (i < Nn) ? cnt[i] : 0;
        int inc = v;
        #pragma unroll
        for (int o = 1; o < 32; o <<= 1) {
            int t = __shfl_up_sync(0xFFFFFFFFu, inc, o);
            if (lane >= o) inc += t;
        }
        if (lane == 31) wsum[wid] = inc;
        __syncthreads();
        if (wid == 0) {
            int s = wsum[lane];
            #pragma unroll
            for (int o = 1; o < 32; o <<= 1) {
                int t = __shfl_up_sync(0xFFFFFFFFu, s, o);
                if (lane >= o) s += t;
            }
            wsum[lane] = s;
        }
        __syncthreads();
        int woff  = wid ? wsum[wid - 1] : 0;
        int total = wsum[31];
        int ex = carry + woff + inc - v;
        if (i < Nn) { rowptr[i] = ex; fill[i] = ex; }
        __syncthreads();
        if (tid == 0) carry += total;
        __syncthreads();
    }
    if (threadIdx.x == 0) rowptr[Nn] = carry;
}
__global__ void k_fill(const void* __restrict__ ei, int* __restrict__ fill,
                       int* __restrict__ colidx) {
    int e = blockIdx.x * blockDim.x + threadIdx.x;
    if (e < Ee) {
        int r = edge_at(ei, 0, e);
        int c = edge_at(ei, 1, e);
        int p = atomicAdd(&fill[r], 1);
        colidx[p] = c;
    }
}

// ---------------- aggregation: fp16 gather, fp32 accumulate, fp16 out ----------------
template <int C, bool GCN>
__global__ void k_agg16(const __half* __restrict__ h, __half* __restrict__ out,
                        const int* __restrict__ rowptr, const int* __restrict__ colidx,
                        const float* __restrict__ dinv, const float* __restrict__ cinv) {
    constexpr int TPN = C / 8;        // lanes per node; 8 halves (16B) per lane
    constexpr int NPB = 256 / TPN;
    int node = blockIdx.x * NPB + threadIdx.x / TPN;
    if (node >= Nn) return;
    int lane = threadIdx.x % TPN;
    int s = rowptr[node], e = rowptr[node + 1];
    const uint4* h4 = (const uint4*)h;
    float acc[8] = {0.f, 0.f, 0.f, 0.f, 0.f, 0.f, 0.f, 0.f};
    for (int p = s; p < e; p++) {
        int j = colidx[p];
        float w = GCN ? dinv[j] : 1.0f;
        uint4 v = __ldg(&h4[(size_t)j * TPN + lane]);
        float2 f0 = __half22float2(*(__half2*)&v.x);
        float2 f1 = __half22float2(*(__half2*)&v.y);
        float2 f2 = __half22float2(*(__half2*)&v.z);
        float2 f3 = __half22float2(*(__half2*)&v.w);
        acc[0] += f0.x * w; acc[1] += f0.y * w;
        acc[2] += f1.x * w; acc[3] += f1.y * w;
        acc[4] += f2.x * w; acc[5] += f2.y * w;
        acc[6] += f3.x * w; acc[7] += f3.y * w;
    }
    float sc = GCN ? dinv[node] : cinv[node];
    __half2 o0 = __floats2half2_rn(acc[0] * sc, acc[1] * sc);
    __half2 o1 = __floats2half2_rn(acc[2] * sc, acc[3] * sc);
    __half2 o2 = __floats2half2_rn(acc[4] * sc, acc[5] * sc);
    __half2 o3 = __floats2half2_rn(acc[6] * sc, acc[7] * sc);
    uint4 u;
    u.x = *(uint32_t*)&o0; u.y = *(uint32_t*)&o1;
    u.z = *(uint32_t*)&o2; u.w = *(uint32_t*)&o3;
    ((uint4*)out)[(size_t)node * TPN + lane] = u;
}

// ---------------- fp16 HMMA dual GEMM, cp.async double-buffered ----------------
#define TM 128
#define TN 128
#define TK 32
#define ROWW 20
#define SB_OFF 2560
#define STG_W 5120
#define SMEM_GT (2 * STG_W * 4)

__global__ void __launch_bounds__(256)
k_gemm_tc(const __half* __restrict__ A0, const __half* __restrict__ B0,
          const __half* __restrict__ A1, const __half* __restrict__ B1,
          const float* __restrict__ bias,
          const float* __restrict__ res, const float* __restrict__ alphaPtr, int alphaIdx,
          float* __restrict__ out, __half* __restrict__ outT,
          int n, int K, int Cout, int doRelu) {
    extern __shared__ uint32_t smem[];
    int tid = threadIdx.x, lane = tid & 31, wid = tid >> 5;
    int gid = lane >> 2, tig = lane & 3;
    int warp_m = wid >> 1, warp_n = wid & 1;
    int bm = blockIdx.y * TM, bn = blockIdx.x * TN;

    int lrow = tid >> 1, lq = tid & 1;
    int agr = min(bm + lrow, n - 1);
    int bgn = min(bn + lrow, Cout - 1);
    uint32_t sbase = smem_u32(smem);

    int nc0 = K / TK;
    int nc = A1 ? 2 * nc0 : nc0;

    #define PREFETCH(ci, buf) do { \
        int _p = (ci) >= nc0; \
        const __half* _A = _p ? A1 : A0; \
        const __half* _B = _p ? B1 : B0; \
        int _k0 = ((ci) - _p * nc0) * TK; \
        uint32_t _sa = sbase + ((buf) * STG_W + lrow * ROWW + lq * 8) * 4; \
        const __half* _ga = &_A[(size_t)agr * K + _k0 + lq * 16]; \
        cpa16(_sa,      _ga); \
        cpa16(_sa + 16, _ga + 8); \
        uint32_t _sb = sbase + ((buf) * STG_W + SB_OFF + lrow * ROWW + lq * 8) * 4; \
        const __half* _gb = &_B[(size_t)bgn * K + _k0 + lq * 16]; \
        cpa16(_sb,      _gb); \
        cpa16(_sb + 16, _gb + 8); \
        asm volatile("cp.async.commit_group;"); \
    } while (0)

    float acc[2][8][4];
    #pragma unroll
    for (int i = 0; i < 2; i++)
        #pragma unroll
        for (int j = 0; j < 8; j++)
            #pragma unroll
            for (int u = 0; u < 4; u++) acc[i][j][u] = 0.f;

    PREFETCH(0, 0);
    #pragma unroll 1
    for (int ci = 0; ci < nc; ci++) {
        int buf = ci & 1;
        if (ci + 1 < nc) {
            PREFETCH(ci + 1, buf ^ 1);
            asm volatile("cp.async.wait_group 1;");
        } else {
            asm volatile("cp.async.wait_group 0;");
        }
        __syncthreads();
        const uint32_t* sAb = smem + buf * STG_W;
        const uint32_t* sBb = smem + buf * STG_W + SB_OFF;
        #pragma unroll
        for (int ks = 0; ks < 2; ks++) {
            int kw = ks * 8;
            uint32_t af[2][4];
            #pragma unroll
            for (int ma = 0; ma < 2; ma++) {
                int m0 = warp_m * 32 + ma * 16;
                af[ma][0] = sAb[(m0 + gid) * ROWW + kw + tig];
                af[ma][1] = sAb[(m0 + gid + 8) * ROWW + kw + tig];
                af[ma][2] = sAb[(m0 + gid) * ROWW + kw + tig + 4];
                af[ma][3] = sAb[(m0 + gid + 8) * ROWW + kw + tig + 4];
            }
            #pragma unroll
            for (int na = 0; na < 8; na++) {
                int n0 = warp_n * 64 + na * 8;
                uint32_t bf[2];
                bf[0] = sBb[(n0 + gid) * ROWW + kw + tig];
                bf[1] = sBb[(n0 + gid) * ROWW + kw + tig + 4];
                mma16(acc[0][na], af[0], bf);
                mma16(acc[1][na], af[1], bf);
            }
        }
        __syncthreads();
    }
    #undef PREFETCH

    float alpha = alphaPtr ? __ldg(&alphaPtr[alphaIdx]) : 0.f;
    #pragma unroll
    for (int ma = 0; ma < 2; ma++) {
        #pragma unroll
        for (int na = 0; na < 8; na++) {
            int gc = bn + warp_n * 64 + na * 8 + tig * 2;
            #pragma unroll
            for (int half = 0; half < 2; half++) {
                int gr = bm + warp_m * 32 + ma * 16 + gid + half * 8;
                if (gr >= n) continue;
                float v0 = acc[ma][na][half * 2 + 0];
                float v1 = acc[ma][na][half * 2 + 1];
                if (gc + 1 < Cout) {
                    v0 += __ldg(&bias[gc]);
                    v1 += __ldg(&bias[gc + 1]);
                    if (doRelu) { v0 = fmaxf(v0, 0.f); v1 = fmaxf(v1, 0.f); }
                    if (res) {
                        const float2 rv = *(const float2*)&res[(size_t)gr * Cout + gc];
                        v0 = rv.x + alpha * v0;
                        v1 = rv.y + alpha * v1;
                    }
                    float2 o; o.x = v0; o.y = v1;
                    *(float2*)&out[(size_t)gr * Cout + gc] = o;
                    if (outT) {
                        __half2 t = __floats2half2_rn(v0, v1);
                        *(__half2*)&outT[(size_t)gr * Cout + gc] = t;
                    }
                } else if (gc < Cout) {
                    v0 += __ldg(&bias[gc]);
                    if (doRelu) v0 = fmaxf(v0, 0.f);
                    if (res) v0 = res[(size_t)gr * Cout + gc] + alpha * v0;
                    out[(size_t)gr * Cout + gc] = v0;
                    if (outT) outT[(size_t)gr * Cout + gc] = __float2half_rn(v0);
                }
            }
        }
    }
}

// ---------------- launch ----------------
extern "C" void kernel_launch(void* const* d_in, const int* in_sizes, int n_in,
                              void* d_out, int out_size) {
    const float* x     = (const float*)d_in[0];
    const void*  ei    = d_in[1];
    const float* alpha = (const float*)d_in[2];
    const float* W0 = (const float*)d_in[3];  const float* b0 = (const float*)d_in[4];
    const float* W1 = (const float*)d_in[5];  const float* R1 = (const float*)d_in[6];  const float* b1 = (const float*)d_in[7];
    const float* W2 = (const float*)d_in[8];  const float* R2 = (const float*)d_in[9];  const float* b2 = (const float*)d_in[10];
    const float* W3 = (const float*)d_in[11]; const float* b3 = (const float*)d_in[12];
    const float* W4 = (const float*)d_in[13]; const float* R4 = (const float*)d_in[14]; const float* b4 = (const float*)d_in[15];
    float* out = (float*)d_out;

    float *hA, *hB, *dinv, *cinv;
    __half *hAT, *hBT, *agg, *w16, *x16;
    int *degi, *rowptr, *fill, *colidx;
    cudaGetSymbolAddress((void**)&degi,   g_degi);
    cudaGetSymbolAddress((void**)&dinv,   g_dinv);
    cudaGetSymbolAddress((void**)&cinv,   g_cinv);
    cudaGetSymbolAddress((void**)&rowptr, g_rowptr);
    cudaGetSymbolAddress((void**)&fill,   g_fill);
    cudaGetSymbolAddress((void**)&colidx, g_colidx);
    cudaGetSymbolAddress((void**)&hA,     g_hA);
    cudaGetSymbolAddress((void**)&hB,     g_hB);
    cudaGetSymbolAddress((void**)&hAT,    g_hAT);
    cudaGetSymbolAddress((void**)&hBT,    g_hBT);
    cudaGetSymbolAddress((void**)&agg,    g_agg);
    cudaGetSymbolAddress((void**)&w16,    g_w16);
    cudaGetSymbolAddress((void**)&x16,    g_x16);

    cudaFuncSetAttribute(k_gemm_tc, cudaFuncAttributeMaxDynamicSharedMemorySize, SMEM_GT);

    const int NB_N = (Nn + 255) / 256;
    const int NB_E = (Ee + 255) / 256;
    const int MT   = (Nn + TM - 1) / TM;   // 782

    k_detect<<<1, 32>>>((const int*)ei);
    k_cvtW<<<(WTF_TOTAL + 255) / 256, 256>>>(W0, W1, R1, W2, R2, W3, W4, R4);
    k_cvtX<<<(Nn * 128 / 8 + 255) / 256, 256>>>(x, x16);
    k_zero<<<NB_N, 256>>>(degi, Nn);
    k_count<<<NB_E, 256>>>(ei, degi);
    k_stats<<<NB_N, 256>>>(degi, dinv, cinv);
    k_scan<<<1, 1024>>>(degi, rowptr, fill);
    k_fill<<<NB_E, 256>>>(ei, fill, colidx);

    // layer 0: GCN, 128->128, rezero residual alpha[0]; hA + fp16 copy
    k_agg16<128, true><<<Nn / 16, 256>>>(x16, agg, rowptr, colidx, dinv, cinv);
    k_gemm_tc<<<dim3(1, MT), 256, SMEM_GT>>>(agg, w16 + 0, nullptr, nullptr, b0, x, alpha, 0,
                                             hA, hAT, Nn, 128, 128, 0);

    // layer 1: SAGE 128->256 + relu; hB + fp16 copy
    k_agg16<128, false><<<Nn / 16, 256>>>(hAT, agg, rowptr, colidx, dinv, cinv);
    k_gemm_tc<<<dim3(2, MT), 256, SMEM_GT>>>(agg, w16 + 16384, hAT, w16 + 49152, b1,
                                             nullptr, nullptr, 0, hB, hBT, Nn, 128, 256, 1);

    // layer 2: SAGE 256->256 + relu; hA + fp16 copy (L3 agg + L3 residual need it)
    k_agg16<256, false><<<Nn / 8, 256>>>(hBT, agg, rowptr, colidx, dinv, cinv);
    k_gemm_tc<<<dim3(2, MT), 256, SMEM_GT>>>(agg, w16 + 81920, hBT, w16 + 147456, b2,
                                             nullptr, nullptr, 0, hA, hAT, Nn, 256, 256, 1);

    // layer 3: GCN, 256->256, rezero residual alpha[3]; hB + fp16 copy
    k_agg16<256, true><<<Nn / 8, 256>>>(hAT, agg, rowptr, colidx, dinv, cinv);
    k_gemm_tc<<<dim3(2, MT), 256, SMEM_GT>>>(agg, w16 + 212992, nullptr, nullptr, b3,
                                             hA, alpha, 3, hB, hBT, Nn, 256, 256, 0);

    // layer 4: SAGE 256->112, no relu
    k_agg16<256, false><<<Nn / 8, 256>>>(hBT, agg, rowptr, colidx, dinv, cinv);
    k_gemm_tc<<<dim3(1, MT), 256, SMEM_GT>>>(agg, w16 + 278528, hBT, w16 + 307200, b4,
                                             nullptr, nullptr, 0, out, nullptr, Nn, 256, 112, 0);
}

// round 14
// speedup vs baseline: 3.2659x; 1.0118x over previous
#include <cuda_runtime.h>
#include <cuda_fp16.h>
#include <cstdint>

#define Nn 100000
#define Ee 800000

// ---------------- scratch (static __device__ globals; no runtime alloc) ----------------
__device__ int    g_is64;
__device__ int    g_degi[Nn];
__device__ float  g_dinv[Nn];
__device__ float  g_cinv[Nn];
__device__ int    g_rowptr[Nn + 1];
__device__ int    g_fill[Nn];
__device__ int    g_colidx[Ee];
__device__ float  g_hA [(size_t)Nn * 256];
__device__ float  g_hB [(size_t)Nn * 256];
__device__ __half g_hAT[(size_t)Nn * 256];
__device__ __half g_hBT[(size_t)Nn * 256];
__device__ __half g_agg[(size_t)Nn * 256];
__device__ __half g_x16[(size_t)Nn * 128];
#define WTF_TOTAL 335872
__device__ __half g_w16[WTF_TOTAL];

__device__ __forceinline__ void mma16(float* d, const uint32_t* a, const uint32_t* b) {
    asm volatile(
        "mma.sync.aligned.m16n8k16.row.col.f32.f16.f16.f32 "
        "{%0,%1,%2,%3}, {%4,%5,%6,%7}, {%8,%9}, {%0,%1,%2,%3};"
        : "+f"(d[0]), "+f"(d[1]), "+f"(d[2]), "+f"(d[3])
        : "r"(a[0]), "r"(a[1]), "r"(a[2]), "r"(a[3]), "r"(b[0]), "r"(b[1]));
}
__device__ __forceinline__ uint32_t smem_u32(const void* p) {
    uint32_t a;
    asm("{ .reg .u64 t; cvta.to.shared.u64 t, %1; cvt.u32.u64 %0, t; }" : "=r"(a) : "l"(p));
    return a;
}
__device__ __forceinline__ void cpa16(uint32_t s, const void* g) {
    asm volatile("cp.async.ca.shared.global [%0], [%1], 16;" :: "r"(s), "l"(g));
}

// ---------------- weight pre-conversion: fp32 [k][n] -> fp16 transposed [n][k] ----------------
__global__ void k_cvtW(const float* __restrict__ W0, const float* __restrict__ W1,
                       const float* __restrict__ R1, const float* __restrict__ W2,
                       const float* __restrict__ R2, const float* __restrict__ W3,
                       const float* __restrict__ W4, const float* __restrict__ R4) {
    int i = blockIdx.x * blockDim.x + threadIdx.x;
    if (i >= WTF_TOTAL) return;
    const float* s; int off, K, C;
    if      (i < 16384)  { s = W0; off = 0;      K = 128; C = 128; }
    else if (i < 49152)  { s = W1; off = 16384;  K = 128; C = 256; }
    else if (i < 81920)  { s = R1; off = 49152;  K = 128; C = 256; }
    else if (i < 147456) { s = W2; off = 81920;  K = 256; C = 256; }
    else if (i < 212992) { s = R2; off = 147456; K = 256; C = 256; }
    else if (i < 278528) { s = W3; off = 212992; K = 256; C = 256; }
    else if (i < 307200) { s = W4; off = 278528; K = 256; C = 112; }
    else                 { s = R4; off = 307200; K = 256; C = 112; }
    int local = i - off;
    int nn = local / K, kk = local % K;
    g_w16[i] = __float2half_rn(s[(size_t)kk * C + nn]);
}

// ---------------- x -> fp16 (vectorized) ----------------
__global__ void k_cvtX(const float* __restrict__ x, __half* __restrict__ x16) {
    int i = blockIdx.x * blockDim.x + threadIdx.x;   // one uint4 out = 8 halves
    if (i >= Nn * 128 / 8) return;
    const float4* s = (const float4*)x;
    float4 a = __ldg(&s[2 * i]);
    float4 b = __ldg(&s[2 * i + 1]);
    __half2 h0 = __floats2half2_rn(a.x, a.y);
    __half2 h1 = __floats2half2_rn(a.z, a.w);
    __half2 h2 = __floats2half2_rn(b.x, b.y);
    __half2 h3 = __floats2half2_rn(b.z, b.w);
    uint4 u;
    u.x = *(uint32_t*)&h0; u.y = *(uint32_t*)&h1;
    u.z = *(uint32_t*)&h2; u.w = *(uint32_t*)&h3;
    ((uint4*)x16)[i] = u;
}

// ---------------- dtype detection: int32 vs int64 edge_index (parallel) ----------------
__global__ void k_detect(const int* __restrict__ w) {
    int lane = threadIdx.x & 31;
    int bad = 0;
    #pragma unroll
    for (int i = lane; i < 256; i += 32)
        if (w[2 * i + 1] != 0) bad = 1;
    unsigned m = __ballot_sync(0xFFFFFFFFu, bad);
    if (lane == 0) g_is64 = (m == 0) ? 1 : 0;
}
__device__ __forceinline__ int edge_at(const void* ei, int half, int e) {
    if (g_is64) return (int)((const long long*)ei)[(size_t)half * Ee + e];
    return ((const int*)ei)[(size_t)half * Ee + e];
}

// ---------------- small kernels ----------------
__global__ void k_zero(int* p, int n) {
    int i = blockIdx.x * blockDim.x + threadIdx.x;
    if (i < n) p[i] = 0;
}
__global__ void k_count(const void* __restrict__ ei, int* __restrict__ degi) {
    int e = blockIdx.x * blockDim.x + threadIdx.x;
    if (e < Ee) atomicAdd(&degi[edge_at(ei, 0, e)], 1);
}
__global__ void k_stats(const int* __restrict__ degi, float* __restrict__ dinv,
                        float* __restrict__ cinv) {
    int i = blockIdx.x * blockDim.x + threadIdx.x;
    if (i < Nn) {
        int d = degi[i];
        dinv[i] = (d > 0) ? rsqrtf((float)d) : 0.0f;
        cinv[i] = 1.0f / (float)max(d, 1);
    }
}
__global__ void k_scan(const int* __restrict__ cnt, int* __restrict__ rowptr,
                       int* __restrict__ fill) {
    __shared__ int wsum[32];
    __shared__ int carry;
    int tid = threadIdx.x, lane = tid & 31, wid = tid >> 5;
    if (tid == 0) carry = 0;
    __syncthreads();
    for (int base = 0; base < Nn; base += 1024) {
        int i = base + tid;
        int v = (i < Nn) ? cnt[i] : 0;
        int inc = v;
        #pragma unroll
        for (int o = 1; o < 32; o <<= 1) {
            int t = __shfl_up_sync(0xFFFFFFFFu, inc, o);
            if (lane >= o) inc += t;
        }
        if (lane == 31) wsum[wid] = inc;
        __syncthreads();
        if (wid == 0) {
            int s = wsum[lane];
            #pragma unroll
            for (int o = 1; o < 32; o <<= 1) {
                int t = __shfl_up_sync(0xFFFFFFFFu, s, o);
                if (lane >= o) s += t;
            }
            wsum[lane] = s;
        }
        __syncthreads();
        int woff  = wid ? wsum[wid - 1] : 0;
        int total = wsum[31];
        int ex = carry + woff + inc - v;
        if (i < Nn) { rowptr[i] = ex; fill[i] = ex; }
        __syncthreads();
        if (tid == 0) carry += total;
        __syncthreads();
    }
    if (threadIdx.x == 0) rowptr[Nn] = carry;
}
__global__ void k_fill(const void* __restrict__ ei, int* __restrict__ fill,
                       int* __restrict__ colidx) {
    int e = blockIdx.x * blockDim.x + threadIdx.x;
    if (e < Ee) {
        int r = edge_at(ei, 0, e);
        int c = edge_at(ei, 1, e);
        int p = atomicAdd(&fill[r], 1);
        colidx[p] = c;
    }
}

// ---------------- aggregation: fp16 gather (2x unrolled), fp32 accumulate, fp16 out ----------------
template <int C, bool GCN>
__global__ void k_agg16(const __half* __restrict__ h, __half* __restrict__ out,
                        const int* __restrict__ rowptr, const int* __restrict__ colidx,
                        const float* __restrict__ dinv, const float* __restrict__ cinv) {
    constexpr int TPN = C / 8;        // lanes per node; 8 halves (16B) per lane
    constexpr int NPB = 256 / TPN;
    int node = blockIdx.x * NPB + threadIdx.x / TPN;
    if (node >= Nn) return;
    int lane = threadIdx.x % TPN;
    int s = rowptr[node], e = rowptr[node + 1];
    const uint4* h4 = (const uint4*)h;
    float acc[8] = {0.f, 0.f, 0.f, 0.f, 0.f, 0.f, 0.f, 0.f};
    int p = s;
    for (; p + 2 <= e; p += 2) {
        int j0 = colidx[p], j1 = colidx[p + 1];
        float w0 = GCN ? dinv[j0] : 1.0f;
        float w1 = GCN ? dinv[j1] : 1.0f;
        uint4 v0 = __ldg(&h4[(size_t)j0 * TPN + lane]);
        uint4 v1 = __ldg(&h4[(size_t)j1 * TPN + lane]);
        float2 a0 = __half22float2(*(__half2*)&v0.x);
        float2 a1 = __half22float2(*(__half2*)&v0.y);
        float2 a2 = __half22float2(*(__half2*)&v0.z);
        float2 a3 = __half22float2(*(__half2*)&v0.w);
        acc[0] += a0.x * w0; acc[1] += a0.y * w0;
        acc[2] += a1.x * w0; acc[3] += a1.y * w0;
        acc[4] += a2.x * w0; acc[5] += a2.y * w0;
        acc[6] += a3.x * w0; acc[7] += a3.y * w0;
        float2 b0 = __half22float2(*(__half2*)&v1.x);
        float2 b1 = __half22float2(*(__half2*)&v1.y);
        float2 b2 = __half22float2(*(__half2*)&v1.z);
        float2 b3 = __half22float2(*(__half2*)&v1.w);
        acc[0] += b0.x * w1; acc[1] += b0.y * w1;
        acc[2] += b1.x * w1; acc[3] += b1.y * w1;
        acc[4] += b2.x * w1; acc[5] += b2.y * w1;
        acc[6] += b3.x * w1; acc[7] += b3.y * w1;
    }
    if (p < e) {
        int j = colidx[p];
        float w = GCN ? dinv[j] : 1.0f;
        uint4 v = __ldg(&h4[(size_t)j * TPN + lane]);
        float2 f0 = __half22float2(*(__half2*)&v.x);
        float2 f1 = __half22float2(*(__half2*)&v.y);
        float2 f2 = __half22float2(*(__half2*)&v.z);
        float2 f3 = __half22float2(*(__half2*)&v.w);
        acc[0] += f0.x * w; acc[1] += f0.y * w;
        acc[2] += f1.x * w; acc[3] += f1.y * w;
        acc[4] += f2.x * w; acc[5] += f2.y * w;
        acc[6] += f3.x * w; acc[7] += f3.y * w;
    }
    float sc = GCN ? dinv[node] : cinv[node];
    __half2 o0 = __floats2half2_rn(acc[0] * sc, acc[1] * sc);
    __half2 o1 = __floats2half2_rn(acc[2] * sc, acc[3] * sc);
    __half2 o2 = __floats2half2_rn(acc[4] * sc, acc[5] * sc);
    __half2 o3 = __floats2half2_rn(acc[6] * sc, acc[7] * sc);
    uint4 u;
    u.x = *(uint32_t*)&o0; u.y = *(uint32_t*)&o1;
    u.z = *(uint32_t*)&o2; u.w = *(uint32_t*)&o3;
    ((uint4*)out)[(size_t)node * TPN + lane] = u;
}

// ---------------- fp16 HMMA dual GEMM, cp.async double-buffered ----------------
#define TM 128
#define TN 128
#define TK 32
#define ROWW 20
#define SB_OFF 2560
#define STG_W 5120
#define SMEM_GT (2 * STG_W * 4)

__global__ void __launch_bounds__(256)
k_gemm_tc(const __half* __restrict__ A0, const __half* __restrict__ B0,
          const __half* __restrict__ A1, const __half* __restrict__ B1,
          const float* __restrict__ bias,
          const float* __restrict__ res, const float* __restrict__ alphaPtr, int alphaIdx,
          float* __restrict__ out, __half* __restrict__ outT,
          int n, int K, int Cout, int doRelu) {
    extern __shared__ uint32_t smem[];
    int tid = threadIdx.x, lane = tid & 31, wid = tid >> 5;
    int gid = lane >> 2, tig = lane & 3;
    int warp_m = wid >> 1, warp_n = wid & 1;
    int bm = blockIdx.y * TM, bn = blockIdx.x * TN;

    int lrow = tid >> 1, lq = tid & 1;
    int agr = min(bm + lrow, n - 1);
    int bgn = min(bn + lrow, Cout - 1);
    uint32_t sbase = smem_u32(smem);

    int nc0 = K / TK;
    int nc = A1 ? 2 * nc0 : nc0;

    #define PREFETCH(ci, buf) do { \
        int _p = (ci) >= nc0; \
        const __half* _A = _p ? A1 : A0; \
        const __half* _B = _p ? B1 : B0; \
        int _k0 = ((ci) - _p * nc0) * TK; \
        uint32_t _sa = sbase + ((buf) * STG_W + lrow * ROWW + lq * 8) * 4; \
        const __half* _ga = &_A[(size_t)agr * K + _k0 + lq * 16]; \
        cpa16(_sa,      _ga); \
        cpa16(_sa + 16, _ga + 8); \
        uint32_t _sb = sbase + ((buf) * STG_W + SB_OFF + lrow * ROWW + lq * 8) * 4; \
        const __half* _gb = &_B[(size_t)bgn * K + _k0 + lq * 16]; \
        cpa16(_sb,      _gb); \
        cpa16(_sb + 16, _gb + 8); \
        asm volatile("cp.async.commit_group;"); \
    } while (0)

    float acc[2][8][4];
    #pragma unroll
    for (int i = 0; i < 2; i++)
        #pragma unroll
        for (int j = 0; j < 8; j++)
            #pragma unroll
            for (int u = 0; u < 4; u++) acc[i][j][u] = 0.f;

    PREFETCH(0, 0);
    #pragma unroll 1
    for (int ci = 0; ci < nc; ci++) {
        int buf = ci & 1;
        if (ci + 1 < nc) {
            PREFETCH(ci + 1, buf ^ 1);
            asm volatile("cp.async.wait_group 1;");
        } else {
            asm volatile("cp.async.wait_group 0;");
        }
        __syncthreads();
        const uint32_t* sAb = smem + buf * STG_W;
        const uint32_t* sBb = smem + buf * STG_W + SB_OFF;
        #pragma unroll
        for (int ks = 0; ks < 2; ks++) {
            int kw = ks * 8;
            uint32_t af[2][4];
            #pragma unroll
            for (int ma = 0; ma < 2; ma++) {
                int m0 = warp_m * 32 + ma * 16;
                af[ma][0] = sAb[(m0 + gid) * ROWW + kw + tig];
                af[ma][1] = sAb[(m0 + gid + 8) * ROWW + kw + tig];
                af[ma][2] = sAb[(m0 + gid) * ROWW + kw + tig + 4];
                af[ma][3] = sAb[(m0 + gid + 8) * ROWW + kw + tig + 4];
            }
            #pragma unroll
            for (int na = 0; na < 8; na++) {
                int n0 = warp_n * 64 + na * 8;
                uint32_t bf[2];
                bf[0] = sBb[(n0 + gid) * ROWW + kw + tig];
                bf[1] = sBb[(n0 + gid) * ROWW + kw + tig + 4];
                mma16(acc[0][na], af[0], bf);
                mma16(acc[1][na], af[1], bf);
            }
        }
        __syncthreads();
    }
    #undef PREFETCH

    float alpha = alphaPtr ? __ldg(&alphaPtr[alphaIdx]) : 0.f;
    #pragma unroll
    for (int ma = 0; ma < 2; ma++) {
        #pragma unroll
        for (int na = 0; na < 8; na++) {
            int gc = bn + warp_n * 64 + na * 8 + tig * 2;
            #pragma unroll
            for (int half = 0; half < 2; half++) {
                int gr = bm + warp_m * 32 + ma * 16 + gid + half * 8;
                if (gr >= n) continue;
                float v0 = acc[ma][na][half * 2 + 0];
                float v1 = acc[ma][na][half * 2 + 1];
                if (gc + 1 < Cout) {
                    v0 += __ldg(&bias[gc]);
                    v1 += __ldg(&bias[gc + 1]);
                    if (doRelu) { v0 = fmaxf(v0, 0.f); v1 = fmaxf(v1, 0.f); }
                    if (res) {
                        const float2 rv = *(const float2*)&res[(size_t)gr * Cout + gc];
                        v0 = rv.x + alpha * v0;
                        v1 = rv.y + alpha * v1;
                    }
                    float2 o; o.x = v0; o.y = v1;
                    *(float2*)&out[(size_t)gr * Cout + gc] = o;
                    if (outT) {
                        __half2 t = __floats2half2_rn(v0, v1);
                        *(__half2*)&outT[(size_t)gr * Cout + gc] = t;
                    }
                } else if (gc < Cout) {
                    v0 += __ldg(&bias[gc]);
                    if (doRelu) v0 = fmaxf(v0, 0.f);
                    if (res) v0 = res[(size_t)gr * Cout + gc] + alpha * v0;
                    out[(size_t)gr * Cout + gc] = v0;
                    if (outT) outT[(size_t)gr * Cout + gc] = __float2half_rn(v0);
                }
            }
        }
    }
}

// ---------------- launch ----------------
extern "C" void kernel_launch(void* const* d_in, const int* in_sizes, int n_in,
                              void* d_out, int out_size) {
    const float* x     = (const float*)d_in[0];
    const void*  ei    = d_in[1];
    const float* alpha = (const float*)d_in[2];
    const float* W0 = (const float*)d_in[3];  const float* b0 = (const float*)d_in[4];
    const float* W1 = (const float*)d_in[5];  const float* R1 = (const float*)d_in[6];  const float* b1 = (const float*)d_in[7];
    const float* W2 = (const float*)d_in[8];  const float* R2 = (const float*)d_in[9];  const float* b2 = (const float*)d_in[10];
    const float* W3 = (const float*)d_in[11]; const float* b3 = (const float*)d_in[12];
    const float* W4 = (const float*)d_in[13]; const float* R4 = (const float*)d_in[14]; const float* b4 = (const float*)d_in[15];
    float* out = (float*)d_out;

    float *hA, *hB, *dinv, *cinv;
    __half *hAT, *hBT, *agg, *w16, *x16;
    int *degi, *rowptr, *fill, *colidx;
    cudaGetSymbolAddress((void**)&degi,   g_degi);
    cudaGetSymbolAddress((void**)&dinv,   g_dinv);
    cudaGetSymbolAddress((void**)&cinv,   g_cinv);
    cudaGetSymbolAddress((void**)&rowptr, g_rowptr);
    cudaGetSymbolAddress((void**)&fill,   g_fill);
    cudaGetSymbolAddress((void**)&colidx, g_colidx);
    cudaGetSymbolAddress((void**)&hA,     g_hA);
    cudaGetSymbolAddress((void**)&hB,     g_hB);
    cudaGetSymbolAddress((void**)&hAT,    g_hAT);
    cudaGetSymbolAddress((void**)&hBT,    g_hBT);
    cudaGetSymbolAddress((void**)&agg,    g_agg);
    cudaGetSymbolAddress((void**)&w16,    g_w16);
    cudaGetSymbolAddress((void**)&x16,    g_x16);

    cudaFuncSetAttribute(k_gemm_tc, cudaFuncAttributeMaxDynamicSharedMemorySize, SMEM_GT);

    const int NB_N = (Nn + 255) / 256;
    const int NB_E = (Ee + 255) / 256;
    const int MT   = (Nn + TM - 1) / TM;   // 782

    k_detect<<<1, 32>>>((const int*)ei);
    k_cvtW<<<(WTF_TOTAL + 255) / 256, 256>>>(W0, W1, R1, W2, R2, W3, W4, R4);
    k_cvtX<<<(Nn * 128 / 8 + 255) / 256, 256>>>(x, x16);
    k_zero<<<NB_N, 256>>>(degi, Nn);
    k_count<<<NB_E, 256>>>(ei, degi);
    k_stats<<<NB_N, 256>>>(degi, dinv, cinv);
    k_scan<<<1, 1024>>>(degi, rowptr, fill);
    k_fill<<<NB_E, 256>>>(ei, fill, colidx);

    // layer 0: GCN, 128->128, rezero residual alpha[0]; hA + fp16 copy
    k_agg16<128, true><<<Nn / 16, 256>>>(x16, agg, rowptr, colidx, dinv, cinv);
    k_gemm_tc<<<dim3(1, MT), 256, SMEM_GT>>>(agg, w16 + 0, nullptr, nullptr, b0, x, alpha, 0,
                                             hA, hAT, Nn, 128, 128, 0);

    // layer 1: SAGE 128->256 + relu; hB + fp16 copy
    k_agg16<128, false><<<Nn / 16, 256>>>(hAT, agg, rowptr, colidx, dinv, cinv);
    k_gemm_tc<<<dim3(2, MT), 256, SMEM_GT>>>(agg, w16 + 16384, hAT, w16 + 49152, b1,
                                             nullptr, nullptr, 0, hB, hBT, Nn, 128, 256, 1);

    // layer 2: SAGE 256->256 + relu; hA + fp16 copy (L3 agg + L3 residual need it)
    k_agg16<256, false><<<Nn / 8, 256>>>(hBT, agg, rowptr, colidx, dinv, cinv);
    k_gemm_tc<<<dim3(2, MT), 256, SMEM_GT>>>(agg, w16 + 81920, hBT, w16 + 147456, b2,
                                             nullptr, nullptr, 0, hA, hAT, Nn, 256, 256, 1);

    // layer 3: GCN, 256->256, rezero residual alpha[3]; hB + fp16 copy
    k_agg16<256, true><<<Nn / 8, 256>>>(hAT, agg, rowptr, colidx, dinv, cinv);
    k_gemm_tc<<<dim3(2, MT), 256, SMEM_GT>>>(agg, w16 + 212992, nullptr, nullptr, b3,
                                             hA, alpha, 3, hB, hBT, Nn, 256, 256, 0);

    // layer 4: SAGE 256->112, no relu
    k_agg16<256, false><<<Nn / 8, 256>>>(hBT, agg, rowptr, colidx, dinv, cinv);
    k_gemm_tc<<<dim3(1, MT), 256, SMEM_GT>>>(agg, w16 + 278528, hBT, w16 + 307200, b4,
                                             nullptr, nullptr, 0, out, nullptr, Nn, 256, 112, 0);
}

// round 15
// speedup vs baseline: 3.6360x; 1.1133x over previous
#include <cuda_runtime.h>
#include <cuda_fp16.h>
#include <cstdint>

#define Nn 100000
#define Ee 800000
#define NSB 98   // scan blocks: 98*1024 >= Nn

// ---------------- scratch (static __device__ globals; no runtime alloc) ----------------
__device__ int    g_is64;
__device__ int    g_degi[Nn];
__device__ float  g_dinv[Nn];
__device__ float  g_cinv[Nn];
__device__ int    g_rowptr[Nn + 1];
__device__ int    g_fill[Nn];
__device__ int    g_colidx[Ee];
__device__ int    g_bsum[NSB];
__device__ int    g_boff[NSB];
__device__ float  g_hA [(size_t)Nn * 256];
__device__ __half g_hAT[(size_t)Nn * 256];
__device__ __half g_hBT[(size_t)Nn * 256];
__device__ __half g_agg[(size_t)Nn * 256];
__device__ __half g_x16[(size_t)Nn * 128];
#define WTF_TOTAL 335872
__device__ __half g_w16[WTF_TOTAL];

__device__ __forceinline__ void mma16(float* d, const uint32_t* a, const uint32_t* b) {
    asm volatile(
        "mma.sync.aligned.m16n8k16.row.col.f32.f16.f16.f32 "
        "{%0,%1,%2,%3}, {%4,%5,%6,%7}, {%8,%9}, {%0,%1,%2,%3};"
        : "+f"(d[0]), "+f"(d[1]), "+f"(d[2]), "+f"(d[3])
        : "r"(a[0]), "r"(a[1]), "r"(a[2]), "r"(a[3]), "r"(b[0]), "r"(b[1]));
}
__device__ __forceinline__ uint32_t smem_u32(const void* p) {
    uint32_t a;
    asm("{ .reg .u64 t; cvta.to.shared.u64 t, %1; cvt.u32.u64 %0, t; }" : "=r"(a) : "l"(p));
    return a;
}
__device__ __forceinline__ void cpa16(uint32_t s, const void* g) {
    asm volatile("cp.async.ca.shared.global [%0], [%1], 16;" :: "r"(s), "l"(g));
}

// ---------------- weight pre-conversion: fp32 [k][n] -> fp16 transposed [n][k] ----------------
__global__ void k_cvtW(const float* __restrict__ W0, const float* __restrict__ W1,
                       const float* __restrict__ R1, const float* __restrict__ W2,
                       const float* __restrict__ R2, const float* __restrict__ W3,
                       const float* __restrict__ W4, const float* __restrict__ R4) {
    int i = blockIdx.x * blockDim.x + threadIdx.x;
    if (i >= WTF_TOTAL) return;
    const float* s; int off, K, C;
    if      (i < 16384)  { s = W0; off = 0;      K = 128; C = 128; }
    else if (i < 49152)  { s = W1; off = 16384;  K = 128; C = 256; }
    else if (i < 81920)  { s = R1; off = 49152;  K = 128; C = 256; }
    else if (i < 147456) { s = W2; off = 81920;  K = 256; C = 256; }
    else if (i < 212992) { s = R2; off = 147456; K = 256; C = 256; }
    else if (i < 278528) { s = W3; off = 212992; K = 256; C = 256; }
    else if (i < 307200) { s = W4; off = 278528; K = 256; C = 112; }
    else                 { s = R4; off = 307200; K = 256; C = 112; }
    int local = i - off;
    int nn = local / K, kk = local % K;
    g_w16[i] = __float2half_rn(s[(size_t)kk * C + nn]);
}

// ---------------- x -> fp16 (vectorized) ----------------
__global__ void k_cvtX(const float* __restrict__ x, __half* __restrict__ x16) {
    int i = blockIdx.x * blockDim.x + threadIdx.x;
    if (i >= Nn * 128 / 8) return;
    const float4* s = (const float4*)x;
    float4 a = __ldg(&s[2 * i]);
    float4 b = __ldg(&s[2 * i + 1]);
    __half2 h0 = __floats2half2_rn(a.x, a.y);
    __half2 h1 = __floats2half2_rn(a.z, a.w);
    __half2 h2 = __floats2half2_rn(b.x, b.y);
    __half2 h3 = __floats2half2_rn(b.z, b.w);
    uint4 u;
    u.x = *(uint32_t*)&h0; u.y = *(uint32_t*)&h1;
    u.z = *(uint32_t*)&h2; u.w = *(uint32_t*)&h3;
    ((uint4*)x16)[i] = u;
}

// ---------------- dtype detection: int32 vs int64 edge_index (parallel) ----------------
__global__ void k_detect(const int* __restrict__ w) {
    int lane = threadIdx.x & 31;
    int bad = 0;
    #pragma unroll
    for (int i = lane; i < 256; i += 32)
        if (w[2 * i + 1] != 0) bad = 1;
    unsigned m = __ballot_sync(0xFFFFFFFFu, bad);
    if (lane == 0) g_is64 = (m == 0) ? 1 : 0;
}
__device__ __forceinline__ int edge_at(const void* ei, int half, int e) {
    if (g_is64) return (int)((const long long*)ei)[(size_t)half * Ee + e];
    return ((const int*)ei)[(size_t)half * Ee + e];
}

// ---------------- graph-build kernels ----------------
__global__ void k_zero(int* p, int n) {
    int i = blockIdx.x * blockDim.x + threadIdx.x;
    if (i < n) p[i] = 0;
}
__global__ void k_count(const void* __restrict__ ei, int* __restrict__ degi) {
    int e = blockIdx.x * blockDim.x + threadIdx.x;
    if (e < Ee) atomicAdd(&degi[edge_at(ei, 0, e)], 1);
}

// scan pass 1: per-block sums of degi
__global__ void k_scan1(const int* __restrict__ cnt, int* __restrict__ bsum) {
    __shared__ int ws[32];
    int i = blockIdx.x * 1024 + threadIdx.x;
    int v = (i < Nn) ? cnt[i] : 0;
    #pragma unroll
    for (int o = 16; o > 0; o >>= 1) v += __shfl_down_sync(0xFFFFFFFFu, v, o);
    if ((threadIdx.x & 31) == 0) ws[threadIdx.x >> 5] = v;
    __syncthreads();
    if (threadIdx.x < 32) {
        int s = ws[threadIdx.x];
        #pragma unroll
        for (int o = 16; o > 0; o >>= 1) s += __shfl_down_sync(0xFFFFFFFFu, s, o);
        if (threadIdx.x == 0) bsum[blockIdx.x] = s;
    }
}
// scan pass 2: exclusive scan of NSB partials (one warp-ish block)
__global__ void k_scan2(const int* __restrict__ bsum, int* __restrict__ boff,
                        int* __restrict__ rowptr) {
    __shared__ int sh[NSB];
    int t = threadIdx.x;
    if (t < NSB) sh[t] = bsum[t];
    __syncthreads();
    if (t == 0) {
        int run = 0;
        for (int b = 0; b < NSB; b++) { int v = sh[b]; sh[b] = run; run += v; }
        rowptr[Nn] = run;
    }
    __syncthreads();
    if (t < NSB) boff[t] = sh[t];
}
// scan pass 3: local exclusive scan + block offset -> rowptr/fill; fused stats
__global__ void k_scan3(const int* __restrict__ cnt, const int* __restrict__ boff,
                        int* __restrict__ rowptr, int* __restrict__ fill,
                        float* __restrict__ dinv, float* __restrict__ cinv) {
    __shared__ int ws[32];
    int tid = threadIdx.x, lane = tid & 31, wid = tid >> 5;
    int i = blockIdx.x * 1024 + tid;
    int v = (i < Nn) ? cnt[i] : 0;
    int inc = v;
    #pragma unroll
    for (int o = 1; o < 32; o <<= 1) {
        int t = __shfl_up_sync(0xFFFFFFFFu, inc, o);
        if (lane >= o) inc += t;
    }
    if (lane == 31) ws[wid] = inc;
    __syncthreads();
    if (wid == 0) {
        int s = (lane < 32) ? ws[lane] : 0;
        #pragma unroll
        for (int o = 1; o < 32; o <<= 1) {
            int t = __shfl_up_sync(0xFFFFFFFFu, s, o);
            if (lane >= o) s += t;
        }
        ws[lane] = s;
    }
    __syncthreads();
    int woff = wid ? ws[wid - 1] : 0;
    if (i < Nn) {
        int ex = boff[blockIdx.x] + woff + inc - v;
        rowptr[i] = ex;
        fill[i] = ex;
        dinv[i] = (v > 0) ? rsqrtf((float)v) : 0.0f;
        cinv[i] = 1.0f / (float)max(v, 1);
    }
}
__global__ void k_fill(const void* __restrict__ ei, int* __restrict__ fill,
                       int* __restrict__ colidx) {
    int e = blockIdx.x * blockDim.x + threadIdx.x;
    if (e < Ee) {
        int r = edge_at(ei, 0, e);
        int c = edge_at(ei, 1, e);
        int p = atomicAdd(&fill[r], 1);
        colidx[p] = c;
    }
}

// ---------------- aggregation: fp16 gather (2x unrolled), fp32 accumulate, fp16 out ----------------
template <int C, bool GCN>
__global__ void k_agg16(const __half* __restrict__ h, __half* __restrict__ out,
                        const int* __restrict__ rowptr, const int* __restrict__ colidx,
                        const float* __restrict__ dinv, const float* __restrict__ cinv) {
    constexpr int TPN = C / 8;
    constexpr int NPB = 256 / TPN;
    int node = blockIdx.x * NPB + threadIdx.x / TPN;
    if (node >= Nn) return;
    int lane = threadIdx.x % TPN;
    int s = rowptr[node], e = rowptr[node + 1];
    const uint4* h4 = (const uint4*)h;
    float acc[8] = {0.f, 0.f, 0.f, 0.f, 0.f, 0.f, 0.f, 0.f};
    int p = s;
    for (; p + 2 <= e; p += 2) {
        int j0 = colidx[p], j1 = colidx[p + 1];
        float w0 = GCN ? dinv[j0] : 1.0f;
        float w1 = GCN ? dinv[j1] : 1.0f;
        uint4 v0 = __ldg(&h4[(size_t)j0 * TPN + lane]);
        uint4 v1 = __ldg(&h4[(size_t)j1 * TPN + lane]);
        float2 a0 = __half22float2(*(__half2*)&v0.x);
        float2 a1 = __half22float2(*(__half2*)&v0.y);
        float2 a2 = __half22float2(*(__half2*)&v0.z);
        float2 a3 = __half22float2(*(__half2*)&v0.w);
        acc[0] += a0.x * w0; acc[1] += a0.y * w0;
        acc[2] += a1.x * w0; acc[3] += a1.y * w0;
        acc[4] += a2.x * w0; acc[5] += a2.y * w0;
        acc[6] += a3.x * w0; acc[7] += a3.y * w0;
        float2 b0 = __half22float2(*(__half2*)&v1.x);
        float2 b1 = __half22float2(*(__half2*)&v1.y);
        float2 b2 = __half22float2(*(__half2*)&v1.z);
        float2 b3 = __half22float2(*(__half2*)&v1.w);
        acc[0] += b0.x * w1; acc[1] += b0.y * w1;
        acc[2] += b1.x * w1; acc[3] += b1.y * w1;
        acc[4] += b2.x * w1; acc[5] += b2.y * w1;
        acc[6] += b3.x * w1; acc[7] += b3.y * w1;
    }
    if (p < e) {
        int j = colidx[p];
        float w = GCN ? dinv[j] : 1.0f;
        uint4 v = __ldg(&h4[(size_t)j * TPN + lane]);
        float2 f0 = __half22float2(*(__half2*)&v.x);
        float2 f1 = __half22float2(*(__half2*)&v.y);
        float2 f2 = __half22float2(*(__half2*)&v.z);
        float2 f3 = __half22float2(*(__half2*)&v.w);
        acc[0] += f0.x * w; acc[1] += f0.y * w;
        acc[2] += f1.x * w; acc[3] += f1.y * w;
        acc[4] += f2.x * w; acc[5] += f2.y * w;
        acc[6] += f3.x * w; acc[7] += f3.y * w;
    }
    float sc = GCN ? dinv[node] : cinv[node];
    __half2 o0 = __floats2half2_rn(acc[0] * sc, acc[1] * sc);
    __half2 o1 = __floats2half2_rn(acc[2] * sc, acc[3] * sc);
    __half2 o2 = __floats2half2_rn(acc[4] * sc, acc[5] * sc);
    __half2 o3 = __floats2half2_rn(acc[6] * sc, acc[7] * sc);
    uint4 u;
    u.x = *(uint32_t*)&o0; u.y = *(uint32_t*)&o1;
    u.z = *(uint32_t*)&o2; u.w = *(uint32_t*)&o3;
    ((uint4*)out)[(size_t)node * TPN + lane] = u;
}

// ---------------- fp16 HMMA dual GEMM, cp.async double-buffered ----------------
#define TM 128
#define TN 128
#define TK 32
#define ROWW 20
#define SB_OFF 2560
#define STG_W 5120
#define SMEM_GT (2 * STG_W * 4)

__global__ void __launch_bounds__(256)
k_gemm_tc(const __half* __restrict__ A0, const __half* __restrict__ B0,
          const __half* __restrict__ A1, const __half* __restrict__ B1,
          const float* __restrict__ bias,
          const float* __restrict__ res, const float* __restrict__ alphaPtr, int alphaIdx,
          float* __restrict__ out, __half* __restrict__ outT,
          int n, int K, int Cout, int doRelu) {
    extern __shared__ uint32_t smem[];
    int tid = threadIdx.x, lane = tid & 31, wid = tid >> 5;
    int gid = lane >> 2, tig = lane & 3;
    int warp_m = wid >> 1, warp_n = wid & 1;
    int bm = blockIdx.y * TM, bn = blockIdx.x * TN;

    int lrow = tid >> 1, lq = tid & 1;
    int agr = min(bm + lrow, n - 1);
    int bgn = min(bn + lrow, Cout - 1);
    uint32_t sbase = smem_u32(smem);

    int nc0 = K / TK;
    int nc = A1 ? 2 * nc0 : nc0;

    #define PREFETCH(ci, buf) do { \
        int _p = (ci) >= nc0; \
        const __half* _A = _p ? A1 : A0; \
        const __half* _B = _p ? B1 : B0; \
        int _k0 = ((ci) - _p * nc0) * TK; \
        uint32_t _sa = sbase + ((buf) * STG_W + lrow * ROWW + lq * 8) * 4; \
        const __half* _ga = &_A[(size_t)agr * K + _k0 + lq * 16]; \
        cpa16(_sa,      _ga); \
        cpa16(_sa + 16, _ga + 8); \
        uint32_t _sb = sbase + ((buf) * STG_W + SB_OFF + lrow * ROWW + lq * 8) * 4; \
        const __half* _gb = &_B[(size_t)bgn * K + _k0 + lq * 16]; \
        cpa16(_sb,      _gb); \
        cpa16(_sb + 16, _gb + 8); \
        asm volatile("cp.async.commit_group;"); \
    } while (0)

    float acc[2][8][4];
    #pragma unroll
    for (int i = 0; i < 2; i++)
        #pragma unroll
        for (int j = 0; j < 8; j++)
            #pragma unroll
            for (int u = 0; u < 4; u++) acc[i][j][u] = 0.f;

    PREFETCH(0, 0);
    #pragma unroll 1
    for (int ci = 0; ci < nc; ci++) {
        int buf = ci & 1;
        if (ci + 1 < nc) {
            PREFETCH(ci + 1, buf ^ 1);
            asm volatile("cp.async.wait_group 1;");
        } else {
            asm volatile("cp.async.wait_group 0;");
        }
        __syncthreads();
        const uint32_t* sAb = smem + buf * STG_W;
        const uint32_t* sBb = smem + buf * STG_W + SB_OFF;
        #pragma unroll
        for (int ks = 0; ks < 2; ks++) {
            int kw = ks * 8;
            uint32_t af[2][4];
            #pragma unroll
            for (int ma = 0; ma < 2; ma++) {
                int m0 = warp_m * 32 + ma * 16;
                af[ma][0] = sAb[(m0 + gid) * ROWW + kw + tig];
                af[ma][1] = sAb[(m0 + gid + 8) * ROWW + kw + tig];
                af[ma][2] = sAb[(m0 + gid) * ROWW + kw + tig + 4];
                af[ma][3] = sAb[(m0 + gid + 8) * ROWW + kw + tig + 4];
            }
            #pragma unroll
            for (int na = 0; na < 8; na++) {
                int n0 = warp_n * 64 + na * 8;
                uint32_t bf[2];
                bf[0] = sBb[(n0 + gid) * ROWW + kw + tig];
                bf[1] = sBb[(n0 + gid) * ROWW + kw + tig + 4];
                mma16(acc[0][na], af[0], bf);
                mma16(acc[1][na], af[1], bf);
            }
        }
        __syncthreads();
    }
    #undef PREFETCH

    float alpha = alphaPtr ? __ldg(&alphaPtr[alphaIdx]) : 0.f;
    #pragma unroll
    for (int ma = 0; ma < 2; ma++) {
        #pragma unroll
        for (int na = 0; na < 8; na++) {
            int gc = bn + warp_n * 64 + na * 8 + tig * 2;
            #pragma unroll
            for (int half = 0; half < 2; half++) {
                int gr = bm + warp_m * 32 + ma * 16 + gid + half * 8;
                if (gr >= n) continue;
                float v0 = acc[ma][na][half * 2 + 0];
                float v1 = acc[ma][na][half * 2 + 1];
                if (gc + 1 < Cout) {
                    v0 += __ldg(&bias[gc]);
                    v1 += __ldg(&bias[gc + 1]);
                    if (doRelu) { v0 = fmaxf(v0, 0.f); v1 = fmaxf(v1, 0.f); }
                    if (res) {
                        const float2 rv = *(const float2*)&res[(size_t)gr * Cout + gc];
                        v0 = rv.x + alpha * v0;
                        v1 = rv.y + alpha * v1;
                    }
                    if (out) {
                        float2 o; o.x = v0; o.y = v1;
                        *(float2*)&out[(size_t)gr * Cout + gc] = o;
                    }
                    if (outT) {
                        __half2 t = __floats2half2_rn(v0, v1);
                        *(__half2*)&outT[(size_t)gr * Cout + gc] = t;
                    }
                } else if (gc < Cout) {
                    v0 += __ldg(&bias[gc]);
                    if (doRelu) v0 = fmaxf(v0, 0.f);
                    if (res) v0 = res[(size_t)gr * Cout + gc] + alpha * v0;
                    if (out) out[(size_t)gr * Cout + gc] = v0;
                    if (outT) outT[(size_t)gr * Cout + gc] = __float2half_rn(v0);
                }
            }
        }
    }
}

// ---------------- launch ----------------
extern "C" void kernel_launch(void* const* d_in, const int* in_sizes, int n_in,
                              void* d_out, int out_size) {
    const float* x     = (const float*)d_in[0];
    const void*  ei    = d_in[1];
    const float* alpha = (const float*)d_in[2];
    const float* W0 = (const float*)d_in[3];  const float* b0 = (const float*)d_in[4];
    const float* W1 = (const float*)d_in[5];  const float* R1 = (const float*)d_in[6];  const float* b1 = (const float*)d_in[7];
    const float* W2 = (const float*)d_in[8];  const float* R2 = (const float*)d_in[9];  const float* b2 = (const float*)d_in[10];
    const float* W3 = (const float*)d_in[11]; const float* b3 = (const float*)d_in[12];
    const float* W4 = (const float*)d_in[13]; const float* R4 = (const float*)d_in[14]; const float* b4 = (const float*)d_in[15];
    float* out = (float*)d_out;

    float *hA, *dinv, *cinv;
    __half *hAT, *hBT, *agg, *w16, *x16;
    int *degi, *rowptr, *fill, *colidx, *bsum, *boff;
    cudaGetSymbolAddress((void**)&degi,   g_degi);
    cudaGetSymbolAddress((void**)&dinv,   g_dinv);
    cudaGetSymbolAddress((void**)&cinv,   g_cinv);
    cudaGetSymbolAddress((void**)&rowptr, g_rowptr);
    cudaGetSymbolAddress((void**)&fill,   g_fill);
    cudaGetSymbolAddress((void**)&colidx, g_colidx);
    cudaGetSymbolAddress((void**)&bsum,   g_bsum);
    cudaGetSymbolAddress((void**)&boff,   g_boff);
    cudaGetSymbolAddress((void**)&hA,     g_hA);
    cudaGetSymbolAddress((void**)&hAT,    g_hAT);
    cudaGetSymbolAddress((void**)&hBT,    g_hBT);
    cudaGetSymbolAddress((void**)&agg,    g_agg);
    cudaGetSymbolAddress((void**)&w16,    g_w16);
    cudaGetSymbolAddress((void**)&x16,    g_x16);

    cudaFuncSetAttribute(k_gemm_tc, cudaFuncAttributeMaxDynamicSharedMemorySize, SMEM_GT);

    const int NB_N = (Nn + 255) / 256;
    const int NB_E = (Ee + 255) / 256;
    const int MT   = (Nn + TM - 1) / TM;   // 782

    k_detect<<<1, 32>>>((const int*)ei);
    k_cvtW<<<(WTF_TOTAL + 255) / 256, 256>>>(W0, W1, R1, W2, R2, W3, W4, R4);
    k_cvtX<<<(Nn * 128 / 8 + 255) / 256, 256>>>(x, x16);
    k_zero<<<NB_N, 256>>>(degi, Nn);
    k_count<<<NB_E, 256>>>(ei, degi);
    k_scan1<<<NSB, 1024>>>(degi, bsum);
    k_scan2<<<1, 128>>>(bsum, boff, rowptr);
    k_scan3<<<NSB, 1024>>>(degi, boff, rowptr, fill, dinv, cinv);
    k_fill<<<NB_E, 256>>>(ei, fill, colidx);

    // layer 0: GCN, 128->128, rezero residual alpha[0]; fp16 out only
    k_agg16<128, true><<<Nn / 16, 256>>>(x16, agg, rowptr, colidx, dinv, cinv);
    k_gemm_tc<<<dim3(1, MT), 256, SMEM_GT>>>(agg, w16 + 0, nullptr, nullptr, b0, x, alpha, 0,
                                             nullptr, hAT, Nn, 128, 128, 0);

    // layer 1: SAGE 128->256 + relu; fp16 out only
    k_agg16<128, false><<<Nn / 16, 256>>>(hAT, agg, rowptr, colidx, dinv, cinv);
    k_gemm_tc<<<dim3(2, MT), 256, SMEM_GT>>>(agg, w16 + 16384, hAT, w16 + 49152, b1,
                                             nullptr, nullptr, 0, nullptr, hBT, Nn, 128, 256, 1);

    // layer 2: SAGE 256->256 + relu; hA fp32 (L3 residual) + fp16
    k_agg16<256, false><<<Nn / 8, 256>>>(hBT, agg, rowptr, colidx, dinv, cinv);
    k_gemm_tc<<<dim3(2, MT), 256, SMEM_GT>>>(agg, w16 + 81920, hBT, w16 + 147456, b2,
                                             nullptr, nullptr, 0, hA, hAT, Nn, 256, 256, 1);

    // layer 3: GCN, 256->256, rezero residual alpha[3]; fp16 out only
    k_agg16<256, true><<<Nn / 8, 256>>>(hAT, agg, rowptr, colidx, dinv, cinv);
    k_gemm_tc<<<dim3(2, MT), 256, SMEM_GT>>>(agg, w16 + 212992, nullptr, nullptr, b3,
                                             hA, alpha, 3, nullptr, hBT, Nn, 256, 256, 0);

    // layer 4: SAGE 256->112, no relu; final fp32 out
    k_agg16<256, false><<<Nn / 8, 256>>>(hBT, agg, rowptr, colidx, dinv, cinv);
    k_gemm_tc<<<dim3(1, MT), 256, SMEM_GT>>>(agg, w16 + 278528, hBT, w16 + 307200, b4,
                                             nullptr, nullptr, 0, out, nullptr, Nn, 256, 112, 0);
}

// round 16
// speedup vs baseline: 3.8558x; 1.0604x over previous
#include <cuda_runtime.h>
#include <cuda_fp16.h>
#include <cstdint>

#define Nn 100000
#define Ee 800000
#define NSB 98   // scan blocks: 98*1024 >= Nn

// ---------------- scratch (static __device__ globals; no runtime alloc) ----------------
__device__ int    g_is64;
__device__ int    g_degi[Nn];
__device__ float  g_dinv[Nn];
__device__ float  g_cinv[Nn];
__device__ int    g_rowptr[Nn + 1];
__device__ int    g_fill[Nn];
__device__ int    g_colidx[Ee];
__device__ int    g_bsum[NSB];
__device__ int    g_boff[NSB];
__device__ float  g_hA [(size_t)Nn * 256];
__device__ __half g_hAT[(size_t)Nn * 256];
__device__ __half g_hBT[(size_t)Nn * 256];
__device__ __half g_agg[(size_t)Nn * 256];
__device__ __half g_x16[(size_t)Nn * 128];
#define WTF_TOTAL 335872
__device__ __half g_w16[WTF_TOTAL];

__device__ __forceinline__ void mma16(float* d, const uint32_t* a, const uint32_t* b) {
    asm volatile(
        "mma.sync.aligned.m16n8k16.row.col.f32.f16.f16.f32 "
        "{%0,%1,%2,%3}, {%4,%5,%6,%7}, {%8,%9}, {%0,%1,%2,%3};"
        : "+f"(d[0]), "+f"(d[1]), "+f"(d[2]), "+f"(d[3])
        : "r"(a[0]), "r"(a[1]), "r"(a[2]), "r"(a[3]), "r"(b[0]), "r"(b[1]));
}
__device__ __forceinline__ void ldsm4(uint32_t& r0, uint32_t& r1, uint32_t& r2,
                                      uint32_t& r3, uint32_t addr) {
    asm volatile("ldmatrix.sync.aligned.m8n8.x4.shared.b16 {%0,%1,%2,%3}, [%4];"
                 : "=r"(r0), "=r"(r1), "=r"(r2), "=r"(r3) : "r"(addr));
}
__device__ __forceinline__ uint32_t smem_u32(const void* p) {
    uint32_t a;
    asm("{ .reg .u64 t; cvta.to.shared.u64 t, %1; cvt.u32.u64 %0, t; }" : "=r"(a) : "l"(p));
    return a;
}
__device__ __forceinline__ void cpa16(uint32_t s, const void* g) {
    asm volatile("cp.async.ca.shared.global [%0], [%1], 16;" :: "r"(s), "l"(g));
}

// ---------------- weight pre-conversion: fp32 [k][n] -> fp16 transposed [n][k] ----------------
__global__ void k_cvtW(const float* __restrict__ W0, const float* __restrict__ W1,
                       const float* __restrict__ R1, const float* __restrict__ W2,
                       const float* __restrict__ R2, const float* __restrict__ W3,
                       const float* __restrict__ W4, const float* __restrict__ R4) {
    int i = blockIdx.x * blockDim.x + threadIdx.x;
    if (i >= WTF_TOTAL) return;
    const float* s; int off, K, C;
    if      (i < 16384)  { s = W0; off = 0;      K = 128; C = 128; }
    else if (i < 49152)  { s = W1; off = 16384;  K = 128; C = 256; }
    else if (i < 81920)  { s = R1; off = 49152;  K = 128; C = 256; }
    else if (i < 147456) { s = W2; off = 81920;  K = 256; C = 256; }
    else if (i < 212992) { s = R2; off = 147456; K = 256; C = 256; }
    else if (i < 278528) { s = W3; off = 212992; K = 256; C = 256; }
    else if (i < 307200) { s = W4; off = 278528; K = 256; C = 112; }
    else                 { s = R4; off = 307200; K = 256; C = 112; }
    int local = i - off;
    int nn = local / K, kk = local % K;
    g_w16[i] = __float2half_rn(s[(size_t)kk * C + nn]);
}

// ---------------- x -> fp16 (vectorized) ----------------
__global__ void k_cvtX(const float* __restrict__ x, __half* __restrict__ x16) {
    int i = blockIdx.x * blockDim.x + threadIdx.x;
    if (i >= Nn * 128 / 8) return;
    const float4* s = (const float4*)x;
    float4 a = __ldg(&s[2 * i]);
    float4 b = __ldg(&s[2 * i + 1]);
    __half2 h0 = __floats2half2_rn(a.x, a.y);
    __half2 h1 = __floats2half2_rn(a.z, a.w);
    __half2 h2 = __floats2half2_rn(b.x, b.y);
    __half2 h3 = __floats2half2_rn(b.z, b.w);
    uint4 u;
    u.x = *(uint32_t*)&h0; u.y = *(uint32_t*)&h1;
    u.z = *(uint32_t*)&h2; u.w = *(uint32_t*)&h3;
    ((uint4*)x16)[i] = u;
}

// ---------------- dtype detection: int32 vs int64 edge_index (parallel) ----------------
__global__ void k_detect(const int* __restrict__ w) {
    int lane = threadIdx.x & 31;
    int bad = 0;
    #pragma unroll
    for (int i = lane; i < 256; i += 32)
        if (w[2 * i + 1] != 0) bad = 1;
    unsigned m = __ballot_sync(0xFFFFFFFFu, bad);
    if (lane == 0) g_is64 = (m == 0) ? 1 : 0;
}
__device__ __forceinline__ int edge_at(const void* ei, int half, int e) {
    if (g_is64) return (int)((const long long*)ei)[(size_t)half * Ee + e];
    return ((const int*)ei)[(size_t)half * Ee + e];
}

// ---------------- graph-build kernels ----------------
__global__ void k_zero(int* p, int n) {
    int i = blockIdx.x * blockDim.x + threadIdx.x;
    if (i < n) p[i] = 0;
}
__global__ void k_count(const void* __restrict__ ei, int* __restrict__ degi) {
    int e = blockIdx.x * blockDim.x + threadIdx.x;
    if (e < Ee) atomicAdd(&degi[edge_at(ei, 0, e)], 1);
}
__global__ void k_scan1(const int* __restrict__ cnt, int* __restrict__ bsum) {
    __shared__ int ws[32];
    int i = blockIdx.x * 1024 + threadIdx.x;
    int v = (i < Nn) ? cnt[i] : 0;
    #pragma unroll
    for (int o = 16; o > 0; o >>= 1) v += __shfl_down_sync(0xFFFFFFFFu, v, o);
    if ((threadIdx.x & 31) == 0) ws[threadIdx.x >> 5] = v;
    __syncthreads();
    if (threadIdx.x < 32) {
        int s = ws[threadIdx.x];
        #pragma unroll
        for (int o = 16; o > 0; o >>= 1) s += __shfl_down_sync(0xFFFFFFFFu, s, o);
        if (threadIdx.x == 0) bsum[blockIdx.x] = s;
    }
}
__global__ void k_scan2(const int* __restrict__ bsum, int* __restrict__ boff,
                        int* __restrict__ rowptr) {
    __shared__ int sh[NSB];
    int t = threadIdx.x;
    if (t < NSB) sh[t] = bsum[t];
    __syncthreads();
    if (t == 0) {
        int run = 0;
        for (int b = 0; b < NSB; b++) { int v = sh[b]; sh[b] = run; run += v; }
        rowptr[Nn] = run;
    }
    __syncthreads();
    if (t < NSB) boff[t] = sh[t];
}
__global__ void k_scan3(const int* __restrict__ cnt, const int* __restrict__ boff,
                        int* __restrict__ rowptr, int* __restrict__ fill,
                        float* __restrict__ dinv, float* __restrict__ cinv) {
    __shared__ int ws[32];
    int tid = threadIdx.x, lane = tid & 31, wid = tid >> 5;
    int i = blockIdx.x * 1024 + tid;
    int v = (i < Nn) ? cnt[i] : 0;
    int inc = v;
    #pragma unroll
    for (int o = 1; o < 32; o <<= 1) {
        int t = __shfl_up_sync(0xFFFFFFFFu, inc, o);
        if (lane >= o) inc += t;
    }
    if (lane == 31) ws[wid] = inc;
    __syncthreads();
    if (wid == 0) {
        int s = (lane < 32) ? ws[lane] : 0;
        #pragma unroll
        for (int o = 1; o < 32; o <<= 1) {
            int t = __shfl_up_sync(0xFFFFFFFFu, s, o);
            if (lane >= o) s += t;
        }
        ws[lane] = s;
    }
    __syncthreads();
    int woff = wid ? ws[wid - 1] : 0;
    if (i < Nn) {
        int ex = boff[blockIdx.x] + woff + inc - v;
        rowptr[i] = ex;
        fill[i] = ex;
        dinv[i] = (v > 0) ? rsqrtf((float)v) : 0.0f;
        cinv[i] = 1.0f / (float)max(v, 1);
    }
}
__global__ void k_fill(const void* __restrict__ ei, int* __restrict__ fill,
                       int* __restrict__ colidx) {
    int e = blockIdx.x * blockDim.x + threadIdx.x;
    if (e < Ee) {
        int r = edge_at(ei, 0, e);
        int c = edge_at(ei, 1, e);
        int p = atomicAdd(&fill[r], 1);
        colidx[p] = c;
    }
}

// ---------------- aggregation: fp16 gather (2x unrolled), fp32 accumulate, fp16 out ----------------
template <int C, bool GCN>
__global__ void k_agg16(const __half* __restrict__ h, __half* __restrict__ out,
                        const int* __restrict__ rowptr, const int* __restrict__ colidx,
                        const float* __restrict__ dinv, const float* __restrict__ cinv) {
    constexpr int TPN = C / 8;
    constexpr int NPB = 256 / TPN;
    int node = blockIdx.x * NPB + threadIdx.x / TPN;
    if (node >= Nn) return;
    int lane = threadIdx.x % TPN;
    int s = rowptr[node], e = rowptr[node + 1];
    const uint4* h4 = (const uint4*)h;
    float acc[8] = {0.f, 0.f, 0.f, 0.f, 0.f, 0.f, 0.f, 0.f};
    int p = s;
    for (; p + 2 <= e; p += 2) {
        int j0 = colidx[p], j1 = colidx[p + 1];
        float w0 = GCN ? dinv[j0] : 1.0f;
        float w1 = GCN ? dinv[j1] : 1.0f;
        uint4 v0 = __ldg(&h4[(size_t)j0 * TPN + lane]);
        uint4 v1 = __ldg(&h4[(size_t)j1 * TPN + lane]);
        float2 a0 = __half22float2(*(__half2*)&v0.x);
        float2 a1 = __half22float2(*(__half2*)&v0.y);
        float2 a2 = __half22float2(*(__half2*)&v0.z);
        float2 a3 = __half22float2(*(__half2*)&v0.w);
        acc[0] += a0.x * w0; acc[1] += a0.y * w0;
        acc[2] += a1.x * w0; acc[3] += a1.y * w0;
        acc[4] += a2.x * w0; acc[5] += a2.y * w0;
        acc[6] += a3.x * w0; acc[7] += a3.y * w0;
        float2 b0 = __half22float2(*(__half2*)&v1.x);
        float2 b1 = __half22float2(*(__half2*)&v1.y);
        float2 b2 = __half22float2(*(__half2*)&v1.z);
        float2 b3 = __half22float2(*(__half2*)&v1.w);
        acc[0] += b0.x * w1; acc[1] += b0.y * w1;
        acc[2] += b1.x * w1; acc[3] += b1.y * w1;
        acc[4] += b2.x * w1; acc[5] += b2.y * w1;
        acc[6] += b3.x * w1; acc[7] += b3.y * w1;
    }
    if (p < e) {
        int j = colidx[p];
        float w = GCN ? dinv[j] : 1.0f;
        uint4 v = __ldg(&h4[(size_t)j * TPN + lane]);
        float2 f0 = __half22float2(*(__half2*)&v.x);
        float2 f1 = __half22float2(*(__half2*)&v.y);
        float2 f2 = __half22float2(*(__half2*)&v.z);
        float2 f3 = __half22float2(*(__half2*)&v.w);
        acc[0] += f0.x * w; acc[1] += f0.y * w;
        acc[2] += f1.x * w; acc[3] += f1.y * w;
        acc[4] += f2.x * w; acc[5] += f2.y * w;
        acc[6] += f3.x * w; acc[7] += f3.y * w;
    }
    float sc = GCN ? dinv[node] : cinv[node];
    __half2 o0 = __floats2half2_rn(acc[0] * sc, acc[1] * sc);
    __half2 o1 = __floats2half2_rn(acc[2] * sc, acc[3] * sc);
    __half2 o2 = __floats2half2_rn(acc[4] * sc, acc[5] * sc);
    __half2 o3 = __floats2half2_rn(acc[6] * sc, acc[7] * sc);
    uint4 u;
    u.x = *(uint32_t*)&o0; u.y = *(uint32_t*)&o1;
    u.z = *(uint32_t*)&o2; u.w = *(uint32_t*)&o3;
    ((uint4*)out)[(size_t)node * TPN + lane] = u;
}

// ---------------- fp16 HMMA dual GEMM, cp.async double-buffered, ldmatrix frags ----------------
#define TM 128
#define TN 128
#define TK 32
#define ROWW 20
#define SB_OFF 2560
#define STG_W 5120
#define SMEM_GT (2 * STG_W * 4)

__global__ void __launch_bounds__(256)
k_gemm_tc(const __half* __restrict__ A0, const __half* __restrict__ B0,
          const __half* __restrict__ A1, const __half* __restrict__ B1,
          const float* __restrict__ bias,
          const float* __restrict__ res, const float* __restrict__ alphaPtr, int alphaIdx,
          float* __restrict__ out, __half* __restrict__ outT,
          int n, int K, int Cout, int doRelu) {
    extern __shared__ uint32_t smem[];
    int tid = threadIdx.x, lane = tid & 31, wid = tid >> 5;
    int gid = lane >> 2, tig = lane & 3;
    int warp_m = wid >> 1, warp_n = wid & 1;
    int bm = blockIdx.y * TM, bn = blockIdx.x * TN;

    int lrow = tid >> 1, lq = tid & 1;
    int agr = min(bm + lrow, n - 1);
    int bgn = min(bn + lrow, Cout - 1);
    uint32_t sbase = smem_u32(smem);

    // ldmatrix per-lane row/column offsets (in words)
    int rowA = (lane & 15) * ROWW + (lane >> 4) * 4;                        // A 16x16 tile
    int rowB = ((lane & 7) + ((lane >> 4) << 3)) * ROWW + ((lane >> 3) & 1) * 4; // B 2x(8x16)
    int baseA[2] = { (warp_m * 32) * ROWW, (warp_m * 32 + 16) * ROWW };
    int baseB[4];
    #pragma unroll
    for (int p4 = 0; p4 < 4; p4++) baseB[p4] = SB_OFF + (warp_n * 64 + p4 * 16) * ROWW;

    int nc0 = K / TK;
    int nc = A1 ? 2 * nc0 : nc0;

    #define PREFETCH(ci, buf) do { \
        int _p = (ci) >= nc0; \
        const __half* _A = _p ? A1 : A0; \
        const __half* _B = _p ? B1 : B0; \
        int _k0 = ((ci) - _p * nc0) * TK; \
        uint32_t _sa = sbase + ((buf) * STG_W + lrow * ROWW + lq * 8) * 4; \
        const __half* _ga = &_A[(size_t)agr * K + _k0 + lq * 16]; \
        cpa16(_sa,      _ga); \
        cpa16(_sa + 16, _ga + 8); \
        uint32_t _sb = sbase + ((buf) * STG_W + SB_OFF + lrow * ROWW + lq * 8) * 4; \
        const __half* _gb = &_B[(size_t)bgn * K + _k0 + lq * 16]; \
        cpa16(_sb,      _gb); \
        cpa16(_sb + 16, _gb + 8); \
        asm volatile("cp.async.commit_group;"); \
    } while (0)

    float acc[2][8][4];
    #pragma unroll
    for (int i = 0; i < 2; i++)
        #pragma unroll
        for (int j = 0; j < 8; j++)
            #pragma unroll
            for (int u = 0; u < 4; u++) acc[i][j][u] = 0.f;

    PREFETCH(0, 0);
    #pragma unroll 1
    for (int ci = 0; ci < nc; ci++) {
        int buf = ci & 1;
        if (ci + 1 < nc) {
            PREFETCH(ci + 1, buf ^ 1);
            asm volatile("cp.async.wait_group 1;");
        } else {
            asm volatile("cp.async.wait_group 0;");
        }
        __syncthreads();
        uint32_t stg = sbase + (buf * STG_W) * 4;
        #pragma unroll
        for (int ks = 0; ks < 2; ks++) {
            int kw = ks * 8;
            uint32_t af[2][4];
            #pragma unroll
            for (int ma = 0; ma < 2; ma++)
                ldsm4(af[ma][0], af[ma][1], af[ma][2], af[ma][3],
                      stg + (baseA[ma] + rowA + kw) * 4);
            uint32_t bf[8][2];
            #pragma unroll
            for (int p4 = 0; p4 < 4; p4++)
                ldsm4(bf[2 * p4][0], bf[2 * p4][1], bf[2 * p4 + 1][0], bf[2 * p4 + 1][1],
                      stg + (baseB[p4] + rowB + kw) * 4);
            #pragma unroll
            for (int na = 0; na < 8; na++) {
                mma16(acc[0][na], af[0], bf[na]);
                mma16(acc[1][na], af[1], bf[na]);
            }
        }
        __syncthreads();
    }
    #undef PREFETCH

    float alpha = alphaPtr ? __ldg(&alphaPtr[alphaIdx]) : 0.f;
    #pragma unroll
    for (int ma = 0; ma < 2; ma++) {
        #pragma unroll
        for (int na = 0; na < 8; na++) {
            int gc = bn + warp_n * 64 + na * 8 + tig * 2;
            #pragma unroll
            for (int half = 0; half < 2; half++) {
                int gr = bm + warp_m * 32 + ma * 16 + gid + half * 8;
                if (gr >= n) continue;
                float v0 = acc[ma][na][half * 2 + 0];
                float v1 = acc[ma][na][half * 2 + 1];
                if (gc + 1 < Cout) {
                    v0 += __ldg(&bias[gc]);
                    v1 += __ldg(&bias[gc + 1]);
                    if (doRelu) { v0 = fmaxf(v0, 0.f); v1 = fmaxf(v1, 0.f); }
                    if (res) {
                        const float2 rv = *(const float2*)&res[(size_t)gr * Cout + gc];
                        v0 = rv.x + alpha * v0;
                        v1 = rv.y + alpha * v1;
                    }
                    if (out) {
                        float2 o; o.x = v0; o.y = v1;
                        *(float2*)&out[(size_t)gr * Cout + gc] = o;
                    }
                    if (outT) {
                        __half2 t = __floats2half2_rn(v0, v1);
                        *(__half2*)&outT[(size_t)gr * Cout + gc] = t;
                    }
                } else if (gc < Cout) {
                    v0 += __ldg(&bias[gc]);
                    if (doRelu) v0 = fmaxf(v0, 0.f);
                    if (res) v0 = res[(size_t)gr * Cout + gc] + alpha * v0;
                    if (out) out[(size_t)gr * Cout + gc] = v0;
                    if (outT) outT[(size_t)gr * Cout + gc] = __float2half_rn(v0);
                }
            }
        }
    }
}

// ---------------- launch ----------------
extern "C" void kernel_launch(void* const* d_in, const int* in_sizes, int n_in,
                              void* d_out, int out_size) {
    const float* x     = (const float*)d_in[0];
    const void*  ei    = d_in[1];
    const float* alpha = (const float*)d_in[2];
    const float* W0 = (const float*)d_in[3];  const float* b0 = (const float*)d_in[4];
    const float* W1 = (const float*)d_in[5];  const float* R1 = (const float*)d_in[6];  const float* b1 = (const float*)d_in[7];
    const float* W2 = (const float*)d_in[8];  const float* R2 = (const float*)d_in[9];  const float* b2 = (const float*)d_in[10];
    const float* W3 = (const float*)d_in[11]; const float* b3 = (const float*)d_in[12];
    const float* W4 = (const float*)d_in[13]; const float* R4 = (const float*)d_in[14]; const float* b4 = (const float*)d_in[15];
    float* out = (float*)d_out;

    float *hA, *dinv, *cinv;
    __half *hAT, *hBT, *agg, *w16, *x16;
    int *degi, *rowptr, *fill, *colidx, *bsum, *boff;
    cudaGetSymbolAddress((void**)&degi,   g_degi);
    cudaGetSymbolAddress((void**)&dinv,   g_dinv);
    cudaGetSymbolAddress((void**)&cinv,   g_cinv);
    cudaGetSymbolAddress((void**)&rowptr, g_rowptr);
    cudaGetSymbolAddress((void**)&fill,   g_fill);
    cudaGetSymbolAddress((void**)&colidx, g_colidx);
    cudaGetSymbolAddress((void**)&bsum,   g_bsum);
    cudaGetSymbolAddress((void**)&boff,   g_boff);
    cudaGetSymbolAddress((void**)&hA,     g_hA);
    cudaGetSymbolAddress((void**)&hAT,    g_hAT);
    cudaGetSymbolAddress((void**)&hBT,    g_hBT);
    cudaGetSymbolAddress((void**)&agg,    g_agg);
    cudaGetSymbolAddress((void**)&w16,    g_w16);
    cudaGetSymbolAddress((void**)&x16,    g_x16);

    cudaFuncSetAttribute(k_gemm_tc, cudaFuncAttributeMaxDynamicSharedMemorySize, SMEM_GT);

    const int NB_N = (Nn + 255) / 256;
    const int NB_E = (Ee + 255) / 256;
    const int MT   = (Nn + TM - 1) / TM;   // 782

    k_detect<<<1, 32>>>((const int*)ei);
    k_cvtW<<<(WTF_TOTAL + 255) / 256, 256>>>(W0, W1, R1, W2, R2, W3, W4, R4);
    k_cvtX<<<(Nn * 128 / 8 + 255) / 256, 256>>>(x, x16);
    k_zero<<<NB_N, 256>>>(degi, Nn);
    k_count<<<NB_E, 256>>>(ei, degi);
    k_scan1<<<NSB, 1024>>>(degi, bsum);
    k_scan2<<<1, 128>>>(bsum, boff, rowptr);
    k_scan3<<<NSB, 1024>>>(degi, boff, rowptr, fill, dinv, cinv);
    k_fill<<<NB_E, 256>>>(ei, fill, colidx);

    // layer 0: GCN, 128->128, rezero residual alpha[0]; fp16 out only
    k_agg16<128, true><<<Nn / 16, 256>>>(x16, agg, rowptr, colidx, dinv, cinv);
    k_gemm_tc<<<dim3(1, MT), 256, SMEM_GT>>>(agg, w16 + 0, nullptr, nullptr, b0, x, alpha, 0,
                                             nullptr, hAT, Nn, 128, 128, 0);

    // layer 1: SAGE 128->256 + relu; fp16 out only
    k_agg16<128, false><<<Nn / 16, 256>>>(hAT, agg, rowptr, colidx, dinv, cinv);
    k_gemm_tc<<<dim3(2, MT), 256, SMEM_GT>>>(agg, w16 + 16384, hAT, w16 + 49152, b1,
                                             nullptr, nullptr, 0, nullptr, hBT, Nn, 128, 256, 1);

    // layer 2: SAGE 256->256 + relu; hA fp32 (L3 residual) + fp16
    k_agg16<256, false><<<Nn / 8, 256>>>(hBT, agg, rowptr, colidx, dinv, cinv);
    k_gemm_tc<<<dim3(2, MT), 256, SMEM_GT>>>(agg, w16 + 81920, hBT, w16 + 147456, b2,
                                             nullptr, nullptr, 0, hA, hAT, Nn, 256, 256, 1);

    // layer 3: GCN, 256->256, rezero residual alpha[3]; fp16 out only
    k_agg16<256, true><<<Nn / 8, 256>>>(hAT, agg, rowptr, colidx, dinv, cinv);
    k_gemm_tc<<<dim3(2, MT), 256, SMEM_GT>>>(agg, w16 + 212992, nullptr, nullptr, b3,
                                             hA, alpha, 3, nullptr, hBT, Nn, 256, 256, 0);

    // layer 4: SAGE 256->112, no relu; final fp32 out
    k_agg16<256, false><<<Nn / 8, 256>>>(hBT, agg, rowptr, colidx, dinv, cinv);
    k_gemm_tc<<<dim3(1, MT), 256, SMEM_GT>>>(agg, w16 + 278528, hBT, w16 + 307200, b4,
                                             nullptr, nullptr, 0, out, nullptr, Nn, 256, 112, 0);
}